// round 8
// baseline (speedup 1.0000x reference)
#include <cuda_runtime.h>

// Problem constants (fixed by setup_inputs)
#define BATCH 8
#define P 1024
#define Q 1024
#define HXR (P-2)   // 1022
#define HXC (Q-1)   // 1023
#define HYR (P-1)   // 1023
#define HYC (Q-2)   // 1022

#define TX 32       // tile cols
#define WY 8        // warps per block (blockDim.y)
#define KY 4        // outputs per thread (y)
#define TROWS (WY*KY)   // 32 tile rows
#define NT (TX*WY)      // 256 threads
#define MINBLK 4        // 1024 threads/SM -> 64 regs/thread budget

// KF = 0.5 * [-11/6, 3, -3/2, 1/3] ; KB = -0.5 * reversed
#define KF0 (-11.0f/12.0f)
#define KF1 ( 1.5f)
#define KF2 (-0.75f)
#define KF3 ( 1.0f/6.0f)
#define KB0 (-1.0f/6.0f)
#define KB1 ( 0.75f)
#define KB2 (-1.5f)
#define KB3 ( 11.0f/12.0f)

// ===========================================================================
// amper: E_out[y,x] = E[y,x] + S1(Hy) - S2(Hx)
// ===========================================================================
__global__ __launch_bounds__(NT, MINBLK) void amper_tiled(
    const float* __restrict__ E,  int Eb,
    const float* __restrict__ Hx, int Hxb,
    const float* __restrict__ Hy, int Hyb,
    const float* __restrict__ filt,
    float* __restrict__ Eout, int Eob)
{
    __shared__ float sHy[TROWS+7][36];
    __shared__ float sHx[TROWS+2][40];

    const int x0 = blockIdx.x * TX;
    const int y0 = blockIdx.y * TROWS;
    const int b  = blockIdx.z;
    const int tx = threadIdx.x, ty = threadIdx.y;

    // hoist filt loads (overlap with staging)
    float f[3][4];
    #pragma unroll
    for (int i = 0; i < 12; ++i) (&f[0][0])[i] = __ldg(filt + i);

    const float* hy = Hy + b * Hyb;
    const float* hx = Hx + b * Hxb;

    // stage Hy tile (zero-fill OOB), warp-per-row
    for (int row = ty; row < TROWS+7; row += WY) {
        int gy = y0 - 4 + row;
        #pragma unroll
        for (int col = tx; col < 34; col += TX) {
            int gx = x0 - 2 + col;
            float v = 0.0f;
            if ((unsigned)gy < (unsigned)HYR && (unsigned)gx < (unsigned)HYC)
                v = __ldg(hy + gy * HYC + gx);
            sHy[row][col] = v;
        }
    }
    // stage Hx tile
    for (int row = ty; row < TROWS+2; row += WY) {
        int gy = y0 - 2 + row;
        #pragma unroll
        for (int col = tx; col < 39; col += TX) {
            int gx = x0 - 4 + col;
            float v = 0.0f;
            if ((unsigned)gy < (unsigned)HXR && (unsigned)gx < (unsigned)HXC)
                v = __ldg(hx + gy * HXC + gx);
            sHx[row][col] = v;
        }
    }

    __syncthreads();

    const int Y = y0 + ty * KY;
    const int x = x0 + tx;
    const int R  = ty * KY + 4;
    const int RY = ty * KY + 2;
    const int c  = tx + 2;
    const int cx = tx + 4;

    const bool interior = (y0 >= 4) && (y0 + TROWS <= P - 4) &&
                          (x0 >= 2) && (x0 + TX <= Q - 2);

    float acc[KY] = {0.f, 0.f, 0.f, 0.f};

    if (interior) {
        const float hh[8] = {
            KB0, KB1,
            0.5f*f[1][0] + KB2, 0.5f*f[1][1] + KB3,
            0.5f*f[1][2] + KF0, 0.5f*f[1][3] + KF1,
            KF2, KF3
        };
        float w0[4], w2[4];
        #pragma unroll
        for (int d = 0; d < 4; ++d) { w0[d] = 0.5f*f[0][d]; w2[d] = 0.5f*f[2][d]; }

        // ---- S1 (Hy), column-wise, added ----
        {
            float v[KY+3];
            #pragma unroll
            for (int t = 0; t < KY+3; ++t) v[t] = sHy[R-2+t][c-2];
            #pragma unroll
            for (int m = 0; m < KY; ++m)
                #pragma unroll
                for (int d = 0; d < 4; ++d) acc[m] += w0[d]*v[m+d];
        }
        {
            float v[KY+7];
            #pragma unroll
            for (int t = 0; t < KY+7; ++t) v[t] = sHy[R-4+t][c-1];
            #pragma unroll
            for (int m = 0; m < KY; ++m)
                #pragma unroll
                for (int t = 0; t < 8; ++t) acc[m] += hh[t]*v[m+t];
        }
        {
            float v[KY+3];
            #pragma unroll
            for (int t = 0; t < KY+3; ++t) v[t] = sHy[R-2+t][c];
            #pragma unroll
            for (int m = 0; m < KY; ++m)
                #pragma unroll
                for (int d = 0; d < 4; ++d) acc[m] += w2[d]*v[m+d];
        }

        // ---- S2 (Hx), row-wise, subtracted ----
        {
            #pragma unroll
            for (int d = 0; d < 4; ++d) acc[0] -= w0[d]*sHx[RY-2][cx-2+d];
        }
        #pragma unroll
        for (int ro = -1; ro <= 2; ++ro) {
            float v[8];
            #pragma unroll
            for (int t = 0; t < 8; ++t) v[t] = sHx[RY+ro][cx-4+t];
            const int m8 = ro + 1;
            #pragma unroll
            for (int t = 0; t < 8; ++t) acc[m8] -= hh[t]*v[t];
            if (ro <= 1) {
                #pragma unroll
                for (int d = 0; d < 4; ++d) acc[ro+2] -= w0[d]*v[d+2];
            }
            if (ro >= 0) {
                #pragma unroll
                for (int d = 0; d < 4; ++d) acc[ro] -= w2[d]*v[d+2];
            }
        }
        {
            #pragma unroll
            for (int d = 0; d < 4; ++d) acc[3] -= w2[d]*sHx[RY+3][cx-2+d];
        }
    } else {
        const float kf[4] = {KF0, KF1, KF2, KF3};
        const float kb[4] = {KB0, KB1, KB2, KB3};
        #pragma unroll
        for (int m = 0; m < KY; ++m) {
            const int y = Y + m, r = R + m, ry = RY + m;
            float s = 0.0f;
            if (y >= 2 && y <= P-3 && x >= 2 && x <= Q-3) {
                float a = 0.0f;
                #pragma unroll
                for (int di = 0; di < 4; ++di)
                    #pragma unroll
                    for (int dj = 0; dj < 3; ++dj)
                        a += sHy[r-2+di][c-2+dj] * f[dj][di];
                s += 0.5f * a;
            }
            if (x >= 1 && x <= Q-2) {
                if (y <= P-5) {
                    float t = 0.0f;
                    #pragma unroll
                    for (int d = 0; d < 4; ++d) t += sHy[r+d][c-1] * kf[d];
                    s += t;
                }
                if (y >= 4) {
                    float t = 0.0f;
                    #pragma unroll
                    for (int d = 0; d < 4; ++d) t += sHy[r-4+d][c-1] * kb[d];
                    s += t;
                }
            }
            if (y >= 2 && y <= P-3 && x >= 2 && x <= Q-3) {
                float a = 0.0f;
                #pragma unroll
                for (int di = 0; di < 3; ++di)
                    #pragma unroll
                    for (int dj = 0; dj < 4; ++dj)
                        a += sHx[ry-2+di][cx-2+dj] * f[di][dj];
                s -= 0.5f * a;
            }
            if (y >= 1 && y <= P-2) {
                if (x <= Q-5) {
                    float t = 0.0f;
                    #pragma unroll
                    for (int d = 0; d < 4; ++d) t += sHx[ry-1][cx+d] * kf[d];
                    s -= t;
                }
                if (x >= 4) {
                    float t = 0.0f;
                    #pragma unroll
                    for (int d = 0; d < 4; ++d) t += sHx[ry-1][cx-4+d] * kb[d];
                    s -= t;
                }
            }
            acc[m] = s;
        }
    }

    const float* e = E + b * Eb;
    float* eo = Eout + b * Eob;
    #pragma unroll
    for (int m = 0; m < KY; ++m)
        eo[(Y+m) * Q + x] = __ldg(e + (Y+m) * Q + x) + acc[m];
}

// ===========================================================================
// faraday: Hx_out[i,j] = Hx[i,j] - S3(E);  Hy_out[i,j] = Hy[i,j] + S4(E)
// ===========================================================================
__global__ __launch_bounds__(NT, MINBLK) void faraday_tiled(
    const float* __restrict__ E,  int Eb,
    const float* __restrict__ Hx, int Hxb,
    const float* __restrict__ Hy, int Hyb,
    const float* __restrict__ filt,
    float* __restrict__ Hxo, int Hxob,
    float* __restrict__ Hyo, int Hyob)
{
    __shared__ float sE[TROWS+5][40];

    const int j0 = blockIdx.x * TX;
    const int i0 = blockIdx.y * TROWS;
    const int b  = blockIdx.z;
    const int tx = threadIdx.x, ty = threadIdx.y;

    float f[3][4];
    #pragma unroll
    for (int i = 0; i < 12; ++i) (&f[0][0])[i] = __ldg(filt + i);

    const float* e = E + b * Eb;

    for (int row = ty; row < TROWS+5; row += WY) {
        int gi = i0 - 2 + row;
        #pragma unroll
        for (int col = tx; col < TX+5; col += TX) {
            int gj = j0 - 2 + col;
            float v = 0.0f;
            if ((unsigned)gi < (unsigned)P && (unsigned)gj < (unsigned)Q)
                v = __ldg(e + gi * Q + gj);
            sE[row][col] = v;
        }
    }

    __syncthreads();

    const int I = i0 + ty * KY;
    const int j = j0 + tx;
    const int R = ty * KY + 2;
    const int c = tx + 2;

    const bool interior = (i0 >= 2) && (i0 + TROWS <= P - 3) &&
                          (j0 >= 2) && (j0 + TX <= Q - 3);

    if (interior) {
        const float gg[6] = {
            KB0,
            0.5f*f[1][0] + KB1,
            0.5f*f[1][1] + KF0 + KB2,
            0.5f*f[1][2] + KF1 + KB3,
            0.5f*f[1][3] + KF2,
            KF3
        };
        float w0[4], w2[4];
        #pragma unroll
        for (int d = 0; d < 4; ++d) { w0[d] = 0.5f*f[0][d]; w2[d] = 0.5f*f[2][d]; }

        float aHx[KY] = {0.f,0.f,0.f,0.f};
        float aHy[KY] = {0.f,0.f,0.f,0.f};

        {   // col c-2
            float v[KY+2];
            #pragma unroll
            for (int t = 0; t < KY+2; ++t) v[t] = sE[R+t][c-2];
            #pragma unroll
            for (int m = 0; m < KY; ++m) aHx[m] += gg[0]*v[m+1];
        }
        {   // col c-1
            float v[KY+2];
            #pragma unroll
            for (int t = 0; t < KY+2; ++t) v[t] = sE[R+t][c-1];
            #pragma unroll
            for (int m = 0; m < KY; ++m)
                aHx[m] += gg[1]*v[m+1] + w0[0]*v[m] + w2[0]*v[m+2];
        }
        {   // col c
            float v[KY+3];
            #pragma unroll
            for (int t = 0; t < KY+3; ++t) v[t] = sE[R-1+t][c];
            #pragma unroll
            for (int m = 0; m < KY; ++m) {
                aHx[m] += gg[2]*v[m+2] + w0[1]*v[m+1] + w2[1]*v[m+3];
                #pragma unroll
                for (int d = 0; d < 4; ++d) aHy[m] += w0[d]*v[m+d];
            }
        }
        {   // col c+1
            float v[KY+5];
            #pragma unroll
            for (int t = 0; t < KY+5; ++t) v[t] = sE[R-2+t][c+1];
            #pragma unroll
            for (int m = 0; m < KY; ++m) {
                aHx[m] += gg[3]*v[m+3] + w0[2]*v[m+2] + w2[2]*v[m+4];
                #pragma unroll
                for (int t = 0; t < 6; ++t) aHy[m] += gg[t]*v[m+t];
            }
        }
        {   // col c+2
            float v[KY+3];
            #pragma unroll
            for (int t = 0; t < KY+3; ++t) v[t] = sE[R-1+t][c+2];
            #pragma unroll
            for (int m = 0; m < KY; ++m) {
                aHx[m] += gg[4]*v[m+2] + w0[3]*v[m+1] + w2[3]*v[m+3];
                #pragma unroll
                for (int d = 0; d < 4; ++d) aHy[m] += w2[d]*v[m+d];
            }
        }
        {   // col c+3
            float v[KY+2];
            #pragma unroll
            for (int t = 0; t < KY+2; ++t) v[t] = sE[R+t][c+3];
            #pragma unroll
            for (int m = 0; m < KY; ++m) aHx[m] += gg[5]*v[m+1];
        }

        const float* hxi = Hx + b * Hxb;
        const float* hyi = Hy + b * Hyb;
        float* hxo = Hxo + b * Hxob;
        float* hyo = Hyo + b * Hyob;
        #pragma unroll
        for (int m = 0; m < KY; ++m) {
            const int i = I + m;
            hxo[i * HXC + j] = __ldg(hxi + i * HXC + j) - aHx[m];
            hyo[i * HYC + j] = __ldg(hyi + i * HYC + j) + aHy[m];
        }
    } else {
        const float kf[4] = {KF0, KF1, KF2, KF3};
        const float kb[4] = {KB0, KB1, KB2, KB3};
        #pragma unroll
        for (int m = 0; m < KY; ++m) {
            const int i = I + m, r = R + m;
            if (i < HXR && j < HXC) {
                float s = __ldg(Hx + b * Hxb + i * HXC + j);
                if (j >= 1 && j <= Q-3) {
                    float a = 0.0f;
                    #pragma unroll
                    for (int di = 0; di < 3; ++di)
                        #pragma unroll
                        for (int dj = 0; dj < 4; ++dj)
                            a += sE[r+di][c-1+dj] * f[di][dj];
                    s -= 0.5f * a;
                }
                if (j <= Q-4) {
                    float t = 0.0f;
                    #pragma unroll
                    for (int d = 0; d < 4; ++d) t += sE[r+1][c+d] * kf[d];
                    s -= t;
                }
                if (j >= 2) {
                    float t = 0.0f;
                    #pragma unroll
                    for (int d = 0; d < 4; ++d) t += sE[r+1][c-2+d] * kb[d];
                    s -= t;
                }
                Hxo[b * Hxob + i * HXC + j] = s;
            }
            if (i < HYR && j < HYC) {
                float s = __ldg(Hy + b * Hyb + i * HYC + j);
                if (i >= 1 && i <= P-3) {
                    float a = 0.0f;
                    #pragma unroll
                    for (int di = 0; di < 4; ++di)
                        #pragma unroll
                        for (int dj = 0; dj < 3; ++dj)
                            a += sE[r-1+di][c+dj] * f[dj][di];
                    s += 0.5f * a;
                }
                if (i <= P-4) {
                    float t = 0.0f;
                    #pragma unroll
                    for (int d = 0; d < 4; ++d) t += sE[r+d][c+1] * kf[d];
                    s += t;
                }
                if (i >= 2) {
                    float t = 0.0f;
                    #pragma unroll
                    for (int d = 0; d < 4; ++d) t += sE[r-2+d][c+1] * kb[d];
                    s += t;
                }
                Hyo[b * Hyob + i * HYC + j] = s;
            }
        }
    }
}

// ---------------------------------------------------------------------------
// Launch: 2 time steps, results written directly into d_out sections.
// ---------------------------------------------------------------------------
extern "C" void kernel_launch(void* const* d_in, const int* in_sizes, int n_in,
                              void* d_out, int out_size)
{
    const float* E    = (const float*)d_in[0];
    const float* Hx   = (const float*)d_in[1];
    const float* Hy   = (const float*)d_in[2];
    const float* filt = (const float*)d_in[3];
    float* out = (float*)d_out;

    const int E_IN_B  = P * Q;
    const int HX_IN_B = HXR * HXC;
    const int HY_IN_B = HYR * HYC;

    const int E_OUT_B  = 2 * P * Q;
    const int HX_OUT_B = 2 * HXR * HXC;
    const int HY_OUT_B = 2 * HYR * HYC;

    float* En  = out;
    float* Em  = out + P * Q;
    float* Hxn = out + (long long)BATCH * E_OUT_B;
    float* Hxm = Hxn + HXR * HXC;
    float* Hyn = Hxn + (long long)BATCH * HX_OUT_B;
    float* Hym = Hyn + HYR * HYC;

    dim3 blk(TX, WY, 1);
    dim3 g(Q / TX, P / TROWS, BATCH);   // (32, 32, 8)

    // Step 1
    amper_tiled<<<g, blk>>>(E, E_IN_B, Hx, HX_IN_B, Hy, HY_IN_B, filt,
                            En, E_OUT_B);
    faraday_tiled<<<g, blk>>>(En, E_OUT_B, Hx, HX_IN_B, Hy, HY_IN_B, filt,
                              Hxn, HX_OUT_B, Hyn, HY_OUT_B);
    // Step 2
    amper_tiled<<<g, blk>>>(En, E_OUT_B, Hxn, HX_OUT_B, Hyn, HY_OUT_B, filt,
                            Em, E_OUT_B);
    faraday_tiled<<<g, blk>>>(Em, E_OUT_B, Hxn, HX_OUT_B, Hyn, HY_OUT_B, filt,
                              Hxm, HX_OUT_B, Hym, HY_OUT_B);
}

// round 9
// speedup vs baseline: 1.3213x; 1.3213x over previous
#include <cuda_runtime.h>

// Problem constants (fixed by setup_inputs)
#define BATCH 8
#define P 1024
#define Q 1024
#define HXR (P-2)   // 1022
#define HXC (Q-1)   // 1023
#define HYR (P-1)   // 1023
#define HYC (Q-2)   // 1022

#define TX 32       // tile cols
#define WY 8        // warps per block (blockDim.y)
#define KY 4        // outputs per thread (y)
#define TROWS (WY*KY)   // 32 tile rows
#define NT (TX*WY)      // 256 threads
#define MINBLK 6        // 1536 threads/SM -> ~42 regs/thread budget

// KF = 0.5 * [-11/6, 3, -3/2, 1/3] ; KB = -0.5 * reversed
#define KF0 (-11.0f/12.0f)
#define KF1 ( 1.5f)
#define KF2 (-0.75f)
#define KF3 ( 1.0f/6.0f)
#define KB0 (-1.0f/6.0f)
#define KB1 ( 0.75f)
#define KB2 (-1.5f)
#define KB3 ( 11.0f/12.0f)

// ===========================================================================
// amper: E_out[y,x] = E[y,x] + S1(Hy) - S2(Hx)
// ===========================================================================
__global__ __launch_bounds__(NT, MINBLK) void amper_tiled(
    const float* __restrict__ E,  int Eb,
    const float* __restrict__ Hx, int Hxb,
    const float* __restrict__ Hy, int Hyb,
    const float* __restrict__ filt,
    float* __restrict__ Eout, int Eob)
{
    __shared__ float sHy[TROWS+7][36];
    __shared__ float sHx[TROWS+2][40];

    const int x0 = blockIdx.x * TX;
    const int y0 = blockIdx.y * TROWS;
    const int b  = blockIdx.z;
    const int tx = threadIdx.x, ty = threadIdx.y;

    float f[3][4];
    #pragma unroll
    for (int i = 0; i < 12; ++i) (&f[0][0])[i] = __ldg(filt + i);

    const float* hy = Hy + b * Hyb;
    const float* hx = Hx + b * Hxb;

    for (int row = ty; row < TROWS+7; row += WY) {
        int gy = y0 - 4 + row;
        #pragma unroll
        for (int col = tx; col < 34; col += TX) {
            int gx = x0 - 2 + col;
            float v = 0.0f;
            if ((unsigned)gy < (unsigned)HYR && (unsigned)gx < (unsigned)HYC)
                v = __ldg(hy + gy * HYC + gx);
            sHy[row][col] = v;
        }
    }
    for (int row = ty; row < TROWS+2; row += WY) {
        int gy = y0 - 2 + row;
        #pragma unroll
        for (int col = tx; col < 39; col += TX) {
            int gx = x0 - 4 + col;
            float v = 0.0f;
            if ((unsigned)gy < (unsigned)HXR && (unsigned)gx < (unsigned)HXC)
                v = __ldg(hx + gy * HXC + gx);
            sHx[row][col] = v;
        }
    }

    __syncthreads();

    const int Y = y0 + ty * KY;
    const int x = x0 + tx;
    const int R  = ty * KY + 4;
    const int RY = ty * KY + 2;
    const int c  = tx + 2;
    const int cx = tx + 4;

    const bool interior = (y0 >= 4) && (y0 + TROWS <= P - 4) &&
                          (x0 >= 2) && (x0 + TX <= Q - 2);

    float acc[KY] = {0.f, 0.f, 0.f, 0.f};

    if (interior) {
        const float hh[8] = {
            KB0, KB1,
            0.5f*f[1][0] + KB2, 0.5f*f[1][1] + KB3,
            0.5f*f[1][2] + KF0, 0.5f*f[1][3] + KF1,
            KF2, KF3
        };
        float w0[4], w2[4];
        #pragma unroll
        for (int d = 0; d < 4; ++d) { w0[d] = 0.5f*f[0][d]; w2[d] = 0.5f*f[2][d]; }

        // ---- S1 (Hy), column-wise, added ----
        {
            float v[KY+3];
            #pragma unroll
            for (int t = 0; t < KY+3; ++t) v[t] = sHy[R-2+t][c-2];
            #pragma unroll
            for (int m = 0; m < KY; ++m)
                #pragma unroll
                for (int d = 0; d < 4; ++d) acc[m] += w0[d]*v[m+d];
        }
        {
            float v[KY+7];
            #pragma unroll
            for (int t = 0; t < KY+7; ++t) v[t] = sHy[R-4+t][c-1];
            #pragma unroll
            for (int m = 0; m < KY; ++m)
                #pragma unroll
                for (int t = 0; t < 8; ++t) acc[m] += hh[t]*v[m+t];
        }
        {
            float v[KY+3];
            #pragma unroll
            for (int t = 0; t < KY+3; ++t) v[t] = sHy[R-2+t][c];
            #pragma unroll
            for (int m = 0; m < KY; ++m)
                #pragma unroll
                for (int d = 0; d < 4; ++d) acc[m] += w2[d]*v[m+d];
        }

        // ---- S2 (Hx), row-wise, subtracted ----
        {
            #pragma unroll
            for (int d = 0; d < 4; ++d) acc[0] -= w0[d]*sHx[RY-2][cx-2+d];
        }
        #pragma unroll
        for (int ro = -1; ro <= 2; ++ro) {
            float v[8];
            #pragma unroll
            for (int t = 0; t < 8; ++t) v[t] = sHx[RY+ro][cx-4+t];
            const int m8 = ro + 1;
            #pragma unroll
            for (int t = 0; t < 8; ++t) acc[m8] -= hh[t]*v[t];
            if (ro <= 1) {
                #pragma unroll
                for (int d = 0; d < 4; ++d) acc[ro+2] -= w0[d]*v[d+2];
            }
            if (ro >= 0) {
                #pragma unroll
                for (int d = 0; d < 4; ++d) acc[ro] -= w2[d]*v[d+2];
            }
        }
        {
            #pragma unroll
            for (int d = 0; d < 4; ++d) acc[3] -= w2[d]*sHx[RY+3][cx-2+d];
        }
    } else {
        const float kf[4] = {KF0, KF1, KF2, KF3};
        const float kb[4] = {KB0, KB1, KB2, KB3};
        #pragma unroll
        for (int m = 0; m < KY; ++m) {
            const int y = Y + m, r = R + m, ry = RY + m;
            float s = 0.0f;
            if (y >= 2 && y <= P-3 && x >= 2 && x <= Q-3) {
                float a = 0.0f;
                #pragma unroll
                for (int di = 0; di < 4; ++di)
                    #pragma unroll
                    for (int dj = 0; dj < 3; ++dj)
                        a += sHy[r-2+di][c-2+dj] * f[dj][di];
                s += 0.5f * a;
            }
            if (x >= 1 && x <= Q-2) {
                if (y <= P-5) {
                    float t = 0.0f;
                    #pragma unroll
                    for (int d = 0; d < 4; ++d) t += sHy[r+d][c-1] * kf[d];
                    s += t;
                }
                if (y >= 4) {
                    float t = 0.0f;
                    #pragma unroll
                    for (int d = 0; d < 4; ++d) t += sHy[r-4+d][c-1] * kb[d];
                    s += t;
                }
            }
            if (y >= 2 && y <= P-3 && x >= 2 && x <= Q-3) {
                float a = 0.0f;
                #pragma unroll
                for (int di = 0; di < 3; ++di)
                    #pragma unroll
                    for (int dj = 0; dj < 4; ++dj)
                        a += sHx[ry-2+di][cx-2+dj] * f[di][dj];
                s -= 0.5f * a;
            }
            if (y >= 1 && y <= P-2) {
                if (x <= Q-5) {
                    float t = 0.0f;
                    #pragma unroll
                    for (int d = 0; d < 4; ++d) t += sHx[ry-1][cx+d] * kf[d];
                    s -= t;
                }
                if (x >= 4) {
                    float t = 0.0f;
                    #pragma unroll
                    for (int d = 0; d < 4; ++d) t += sHx[ry-1][cx-4+d] * kb[d];
                    s -= t;
                }
            }
            acc[m] = s;
        }
    }

    const float* e = E + b * Eb;
    float* eo = Eout + b * Eob;
    #pragma unroll
    for (int m = 0; m < KY; ++m)
        eo[(Y+m) * Q + x] = __ldg(e + (Y+m) * Q + x) + acc[m];
}

// ===========================================================================
// faraday: Hx_out[i,j] = Hx[i,j] - S3(E);  Hy_out[i,j] = Hy[i,j] + S4(E)
// ===========================================================================
__global__ __launch_bounds__(NT, MINBLK) void faraday_tiled(
    const float* __restrict__ E,  int Eb,
    const float* __restrict__ Hx, int Hxb,
    const float* __restrict__ Hy, int Hyb,
    const float* __restrict__ filt,
    float* __restrict__ Hxo, int Hxob,
    float* __restrict__ Hyo, int Hyob)
{
    __shared__ float sE[TROWS+5][40];

    const int j0 = blockIdx.x * TX;
    const int i0 = blockIdx.y * TROWS;
    const int b  = blockIdx.z;
    const int tx = threadIdx.x, ty = threadIdx.y;

    float f[3][4];
    #pragma unroll
    for (int i = 0; i < 12; ++i) (&f[0][0])[i] = __ldg(filt + i);

    const float* e = E + b * Eb;

    for (int row = ty; row < TROWS+5; row += WY) {
        int gi = i0 - 2 + row;
        #pragma unroll
        for (int col = tx; col < TX+5; col += TX) {
            int gj = j0 - 2 + col;
            float v = 0.0f;
            if ((unsigned)gi < (unsigned)P && (unsigned)gj < (unsigned)Q)
                v = __ldg(e + gi * Q + gj);
            sE[row][col] = v;
        }
    }

    __syncthreads();

    const int I = i0 + ty * KY;
    const int j = j0 + tx;
    const int R = ty * KY + 2;
    const int c = tx + 2;

    const bool interior = (i0 >= 2) && (i0 + TROWS <= P - 3) &&
                          (j0 >= 2) && (j0 + TX <= Q - 3);

    if (interior) {
        const float gg[6] = {
            KB0,
            0.5f*f[1][0] + KB1,
            0.5f*f[1][1] + KF0 + KB2,
            0.5f*f[1][2] + KF1 + KB3,
            0.5f*f[1][3] + KF2,
            KF3
        };
        float w0[4], w2[4];
        #pragma unroll
        for (int d = 0; d < 4; ++d) { w0[d] = 0.5f*f[0][d]; w2[d] = 0.5f*f[2][d]; }

        float aHx[KY] = {0.f,0.f,0.f,0.f};
        float aHy[KY] = {0.f,0.f,0.f,0.f};

        {   // col c-2
            float v[KY+2];
            #pragma unroll
            for (int t = 0; t < KY+2; ++t) v[t] = sE[R+t][c-2];
            #pragma unroll
            for (int m = 0; m < KY; ++m) aHx[m] += gg[0]*v[m+1];
        }
        {   // col c-1
            float v[KY+2];
            #pragma unroll
            for (int t = 0; t < KY+2; ++t) v[t] = sE[R+t][c-1];
            #pragma unroll
            for (int m = 0; m < KY; ++m)
                aHx[m] += gg[1]*v[m+1] + w0[0]*v[m] + w2[0]*v[m+2];
        }
        {   // col c
            float v[KY+3];
            #pragma unroll
            for (int t = 0; t < KY+3; ++t) v[t] = sE[R-1+t][c];
            #pragma unroll
            for (int m = 0; m < KY; ++m) {
                aHx[m] += gg[2]*v[m+2] + w0[1]*v[m+1] + w2[1]*v[m+3];
                #pragma unroll
                for (int d = 0; d < 4; ++d) aHy[m] += w0[d]*v[m+d];
            }
        }
        {   // col c+1
            float v[KY+5];
            #pragma unroll
            for (int t = 0; t < KY+5; ++t) v[t] = sE[R-2+t][c+1];
            #pragma unroll
            for (int m = 0; m < KY; ++m) {
                aHx[m] += gg[3]*v[m+3] + w0[2]*v[m+2] + w2[2]*v[m+4];
                #pragma unroll
                for (int t = 0; t < 6; ++t) aHy[m] += gg[t]*v[m+t];
            }
        }
        {   // col c+2
            float v[KY+3];
            #pragma unroll
            for (int t = 0; t < KY+3; ++t) v[t] = sE[R-1+t][c+2];
            #pragma unroll
            for (int m = 0; m < KY; ++m) {
                aHx[m] += gg[4]*v[m+2] + w0[3]*v[m+1] + w2[3]*v[m+3];
                #pragma unroll
                for (int d = 0; d < 4; ++d) aHy[m] += w2[d]*v[m+d];
            }
        }
        {   // col c+3
            float v[KY+2];
            #pragma unroll
            for (int t = 0; t < KY+2; ++t) v[t] = sE[R+t][c+3];
            #pragma unroll
            for (int m = 0; m < KY; ++m) aHx[m] += gg[5]*v[m+1];
        }

        const float* hxi = Hx + b * Hxb;
        const float* hyi = Hy + b * Hyb;
        float* hxo = Hxo + b * Hxob;
        float* hyo = Hyo + b * Hyob;
        #pragma unroll
        for (int m = 0; m < KY; ++m) {
            const int i = I + m;
            hxo[i * HXC + j] = __ldg(hxi + i * HXC + j) - aHx[m];
            hyo[i * HYC + j] = __ldg(hyi + i * HYC + j) + aHy[m];
        }
    } else {
        const float kf[4] = {KF0, KF1, KF2, KF3};
        const float kb[4] = {KB0, KB1, KB2, KB3};
        #pragma unroll
        for (int m = 0; m < KY; ++m) {
            const int i = I + m, r = R + m;
            if (i < HXR && j < HXC) {
                float s = __ldg(Hx + b * Hxb + i * HXC + j);
                if (j >= 1 && j <= Q-3) {
                    float a = 0.0f;
                    #pragma unroll
                    for (int di = 0; di < 3; ++di)
                        #pragma unroll
                        for (int dj = 0; dj < 4; ++dj)
                            a += sE[r+di][c-1+dj] * f[di][dj];
                    s -= 0.5f * a;
                }
                if (j <= Q-4) {
                    float t = 0.0f;
                    #pragma unroll
                    for (int d = 0; d < 4; ++d) t += sE[r+1][c+d] * kf[d];
                    s -= t;
                }
                if (j >= 2) {
                    float t = 0.0f;
                    #pragma unroll
                    for (int d = 0; d < 4; ++d) t += sE[r+1][c-2+d] * kb[d];
                    s -= t;
                }
                Hxo[b * Hxob + i * HXC + j] = s;
            }
            if (i < HYR && j < HYC) {
                float s = __ldg(Hy + b * Hyb + i * HYC + j);
                if (i >= 1 && i <= P-3) {
                    float a = 0.0f;
                    #pragma unroll
                    for (int di = 0; di < 4; ++di)
                        #pragma unroll
                        for (int dj = 0; dj < 3; ++dj)
                            a += sE[r-1+di][c+dj] * f[dj][di];
                    s += 0.5f * a;
                }
                if (i <= P-4) {
                    float t = 0.0f;
                    #pragma unroll
                    for (int d = 0; d < 4; ++d) t += sE[r+d][c+1] * kf[d];
                    s += t;
                }
                if (i >= 2) {
                    float t = 0.0f;
                    #pragma unroll
                    for (int d = 0; d < 4; ++d) t += sE[r-2+d][c+1] * kb[d];
                    s += t;
                }
                Hyo[b * Hyob + i * HYC + j] = s;
            }
        }
    }
}

// ---------------------------------------------------------------------------
// Launch: 2 time steps, results written directly into d_out sections.
// ---------------------------------------------------------------------------
extern "C" void kernel_launch(void* const* d_in, const int* in_sizes, int n_in,
                              void* d_out, int out_size)
{
    const float* E    = (const float*)d_in[0];
    const float* Hx   = (const float*)d_in[1];
    const float* Hy   = (const float*)d_in[2];
    const float* filt = (const float*)d_in[3];
    float* out = (float*)d_out;

    const int E_IN_B  = P * Q;
    const int HX_IN_B = HXR * HXC;
    const int HY_IN_B = HYR * HYC;

    const int E_OUT_B  = 2 * P * Q;
    const int HX_OUT_B = 2 * HXR * HXC;
    const int HY_OUT_B = 2 * HYR * HYC;

    float* En  = out;
    float* Em  = out + P * Q;
    float* Hxn = out + (long long)BATCH * E_OUT_B;
    float* Hxm = Hxn + HXR * HXC;
    float* Hyn = Hxn + (long long)BATCH * HX_OUT_B;
    float* Hym = Hyn + HYR * HYC;

    dim3 blk(TX, WY, 1);
    dim3 g(Q / TX, P / TROWS, BATCH);   // (32, 32, 8)

    // Step 1
    amper_tiled<<<g, blk>>>(E, E_IN_B, Hx, HX_IN_B, Hy, HY_IN_B, filt,
                            En, E_OUT_B);
    faraday_tiled<<<g, blk>>>(En, E_OUT_B, Hx, HX_IN_B, Hy, HY_IN_B, filt,
                              Hxn, HX_OUT_B, Hyn, HY_OUT_B);
    // Step 2
    amper_tiled<<<g, blk>>>(En, E_OUT_B, Hxn, HX_OUT_B, Hyn, HY_OUT_B, filt,
                            Em, E_OUT_B);
    faraday_tiled<<<g, blk>>>(Em, E_OUT_B, Hxn, HX_OUT_B, Hyn, HY_OUT_B, filt,
                              Hxm, HX_OUT_B, Hym, HY_OUT_B);
}

// round 10
// speedup vs baseline: 1.3443x; 1.0174x over previous
#include <cuda_runtime.h>

// Problem constants (fixed by setup_inputs)
#define BATCH 8
#define P 1024
#define Q 1024
#define HXR (P-2)   // 1022
#define HXC (Q-1)   // 1023
#define HYR (P-1)   // 1023
#define HYC (Q-2)   // 1022

#define TILE 32       // 32x32 output tile per block
#define NT 256        // blockDim = (8, 32)

// KF = 0.5 * [-11/6, 3, -3/2, 1/3] ; KB = -0.5 * reversed
#define KF0 (-11.0f/12.0f)
#define KF1 ( 1.5f)
#define KF2 (-0.75f)
#define KF3 ( 1.0f/6.0f)
#define KB0 (-1.0f/6.0f)
#define KB1 ( 0.75f)
#define KB2 (-1.5f)
#define KB3 ( 11.0f/12.0f)

// ===========================================================================
// amper: E_out[y,x] = E[y,x] + S1(Hy) - S2(Hx)
// Thread (tx,ty): row y = y0+ty, cols x = x0+4*tx+q, q=0..3
// sHy: rows y0-4..y0+34 (39), cols x0-2..x0+32 (35), stride 36
// sHx: rows y0-2..y0+31 (34), cols x0-4..x0+34 (39), stride 40
// ===========================================================================
__global__ __launch_bounds__(NT, 7) void amper_tiled(
    const float* __restrict__ E,  int Eb,
    const float* __restrict__ Hx, int Hxb,
    const float* __restrict__ Hy, int Hyb,
    const float* __restrict__ filt,
    float* __restrict__ Eout, int Eob)
{
    __shared__ float sHy[39][36];
    __shared__ float sHx[34][40];

    const int x0 = blockIdx.x * TILE;
    const int y0 = blockIdx.y * TILE;
    const int b  = blockIdx.z;
    const int tx = threadIdx.x, ty = threadIdx.y;       // tx: 0..7, ty: 0..31
    const int tid  = ty * 8 + tx;
    const int warp = tid >> 5, lane = tid & 31;

    float f[3][4];
    #pragma unroll
    for (int i = 0; i < 12; ++i) (&f[0][0])[i] = __ldg(filt + i);

    const float* hy = Hy + b * Hyb;
    const float* hx = Hx + b * Hxb;

    const bool interior = (y0 >= 4) && (y0 + TILE <= P - 4) &&
                          (x0 >= 2) && (x0 + TILE <= Q - 2);

    if (interior) {
        // unguarded staging (all in-bounds, proven for x0,y0 in [32,960])
        for (int r = warp; r < 39; r += 8) {
            const float* src = hy + (y0 - 4 + r) * HYC + (x0 - 2);
            for (int cc = lane; cc < 35; cc += 32) sHy[r][cc] = __ldg(src + cc);
        }
        for (int r = warp; r < 34; r += 8) {
            const float* src = hx + (y0 - 2 + r) * HXC + (x0 - 4);
            for (int cc = lane; cc < 39; cc += 32) sHx[r][cc] = __ldg(src + cc);
        }
    } else {
        for (int r = warp; r < 39; r += 8) {
            int gy = y0 - 4 + r;
            for (int cc = lane; cc < 35; cc += 32) {
                int gx = x0 - 2 + cc;
                float v = 0.0f;
                if ((unsigned)gy < (unsigned)HYR && (unsigned)gx < (unsigned)HYC)
                    v = __ldg(hy + gy * HYC + gx);
                sHy[r][cc] = v;
            }
        }
        for (int r = warp; r < 34; r += 8) {
            int gy = y0 - 2 + r;
            for (int cc = lane; cc < 39; cc += 32) {
                int gx = x0 - 4 + cc;
                float v = 0.0f;
                if ((unsigned)gy < (unsigned)HXR && (unsigned)gx < (unsigned)HXC)
                    v = __ldg(hx + gy * HXC + gx);
                sHx[r][cc] = v;
            }
        }
    }

    __syncthreads();

    const int col4 = 4 * tx;
    const int RH = ty + 4;   // smem row of y in sHy
    const int RX = ty + 2;   // smem row of y in sHx

    float acc[4] = {0.f, 0.f, 0.f, 0.f};

    if (interior) {
        const float hh[8] = {
            KB0, KB1,
            0.5f*f[1][0] + KB2, 0.5f*f[1][1] + KB3,
            0.5f*f[1][2] + KF0, 0.5f*f[1][3] + KF1,
            KF2, KF3
        };
        float w0[4], w2[4];
        #pragma unroll
        for (int d = 0; d < 4; ++d) { w0[d] = 0.5f*f[0][d]; w2[d] = 0.5f*f[2][d]; }

        // ---- S1 (Hy): rows y-4..y+3; per row, cols v[0..5] = sHy[.][col4..col4+5]
        // 8-tap at col x+q-1 -> v[q+1]; w0 at col x+q-2 -> v[q]; w2 at x+q -> v[q+2]
        #pragma unroll
        for (int t = -4; t <= 3; ++t) {
            const float* rp = &sHy[RH + t][col4];
            float4 A  = *(const float4*)rp;
            float2 Bv = *(const float2*)(rp + 4);
            const float v0 = A.x, v1 = A.y, v2 = A.z, v3 = A.w, v4 = Bv.x, v5 = Bv.y;
            const float hc = hh[t + 4];
            acc[0] += hc * v1; acc[1] += hc * v2; acc[2] += hc * v3; acc[3] += hc * v4;
            if (t >= -2 && t <= 1) {
                const float a0 = w0[t + 2], a2 = w2[t + 2];
                acc[0] += a0 * v0 + a2 * v2;
                acc[1] += a0 * v1 + a2 * v3;
                acc[2] += a0 * v2 + a2 * v4;
                acc[3] += a0 * v3 + a2 * v5;
            }
        }

        // ---- S2 (Hx): row y-1 8-tap over cols x+q-4..x+q+3 -> v[q..q+7]
        {
            const float* rp = &sHx[RX - 1][col4];
            float4 A = *(const float4*)rp;
            float4 B = *(const float4*)(rp + 4);
            float4 C = *(const float4*)(rp + 8);
            const float v[12] = {A.x,A.y,A.z,A.w, B.x,B.y,B.z,B.w, C.x,C.y,C.z,C.w};
            #pragma unroll
            for (int q = 0; q < 4; ++q) {
                float s = 0.0f;
                #pragma unroll
                for (int k = 0; k < 8; ++k) s += hh[k] * v[q + k];
                acc[q] -= s;
            }
        }
        // row y-2: w0 over cols x+q-2..x+q+1 -> smem col4+q+2..col4+q+5
        {
            const float* rp = &sHx[RX - 2][col4];
            float2 A = *(const float2*)(rp + 2);
            float4 B = *(const float4*)(rp + 4);
            const float c8 = rp[8];
            const float v[7] = {A.x, A.y, B.x, B.y, B.z, B.w, c8};
            #pragma unroll
            for (int q = 0; q < 4; ++q)
                acc[q] -= w0[0]*v[q] + w0[1]*v[q+1] + w0[2]*v[q+2] + w0[3]*v[q+3];
        }
        // row y: w2, same columns
        {
            const float* rp = &sHx[RX][col4];
            float2 A = *(const float2*)(rp + 2);
            float4 B = *(const float4*)(rp + 4);
            const float c8 = rp[8];
            const float v[7] = {A.x, A.y, B.x, B.y, B.z, B.w, c8};
            #pragma unroll
            for (int q = 0; q < 4; ++q)
                acc[q] -= w2[0]*v[q] + w2[1]*v[q+1] + w2[2]*v[q+2] + w2[3]*v[q+3];
        }
    } else {
        const float kf[4] = {KF0, KF1, KF2, KF3};
        const float kb[4] = {KB0, KB1, KB2, KB3};
        const int y = y0 + ty;
        #pragma unroll
        for (int q = 0; q < 4; ++q) {
            const int x = x0 + col4 + q;
            const int c = col4 + q + 2;    // sHy col of x
            const int cx = col4 + q + 4;   // sHx col of x
            float s = 0.0f;
            // S1
            if (y >= 2 && y <= P-3 && x >= 2 && x <= Q-3) {
                float a = 0.0f;
                #pragma unroll
                for (int di = 0; di < 4; ++di)
                    #pragma unroll
                    for (int dj = 0; dj < 3; ++dj)
                        a += sHy[RH-2+di][c-2+dj] * f[dj][di];
                s += 0.5f * a;
            }
            if (x >= 1 && x <= Q-2) {
                if (y <= P-5) {
                    float t = 0.0f;
                    #pragma unroll
                    for (int d = 0; d < 4; ++d) t += sHy[RH+d][c-1] * kf[d];
                    s += t;
                }
                if (y >= 4) {
                    float t = 0.0f;
                    #pragma unroll
                    for (int d = 0; d < 4; ++d) t += sHy[RH-4+d][c-1] * kb[d];
                    s += t;
                }
            }
            // S2
            if (y >= 2 && y <= P-3 && x >= 2 && x <= Q-3) {
                float a = 0.0f;
                #pragma unroll
                for (int di = 0; di < 3; ++di)
                    #pragma unroll
                    for (int dj = 0; dj < 4; ++dj)
                        a += sHx[RX-2+di][cx-2+dj] * f[di][dj];
                s -= 0.5f * a;
            }
            if (y >= 1 && y <= P-2) {
                if (x <= Q-5) {
                    float t = 0.0f;
                    #pragma unroll
                    for (int d = 0; d < 4; ++d) t += sHx[RX-1][cx+d] * kf[d];
                    s -= t;
                }
                if (x >= 4) {
                    float t = 0.0f;
                    #pragma unroll
                    for (int d = 0; d < 4; ++d) t += sHx[RX-1][cx-4+d] * kb[d];
                    s -= t;
                }
            }
            acc[q] = s;
        }
    }

    // epilogue: E is full-grid and 16B-aligned at x0+4tx (Q=1024)
    const int y = y0 + ty;
    const float* ep = E + b * Eb + y * Q + x0 + col4;
    float4 ev = *(const float4*)ep;
    float4 o;
    o.x = ev.x + acc[0]; o.y = ev.y + acc[1];
    o.z = ev.z + acc[2]; o.w = ev.w + acc[3];
    *(float4*)(Eout + b * Eob + y * Q + x0 + col4) = o;
}

// ===========================================================================
// faraday: Hx_out[i,j] = Hx[i,j] - S3(E);  Hy_out[i,j] = Hy[i,j] + S4(E)
// Thread (tx,ty): row i = i0+ty, cols j = j0+4*tx+q, q=0..3
// sE: rows i0-2..i0+34 (37), cols j0-2..j0+34 (37), stride 40
// ===========================================================================
__global__ __launch_bounds__(NT, 7) void faraday_tiled(
    const float* __restrict__ E,  int Eb,
    const float* __restrict__ Hx, int Hxb,
    const float* __restrict__ Hy, int Hyb,
    const float* __restrict__ filt,
    float* __restrict__ Hxo, int Hxob,
    float* __restrict__ Hyo, int Hyob)
{
    __shared__ float sE[37][40];

    const int j0 = blockIdx.x * TILE;
    const int i0 = blockIdx.y * TILE;
    const int b  = blockIdx.z;
    const int tx = threadIdx.x, ty = threadIdx.y;
    const int tid  = ty * 8 + tx;
    const int warp = tid >> 5, lane = tid & 31;

    float f[3][4];
    #pragma unroll
    for (int i = 0; i < 12; ++i) (&f[0][0])[i] = __ldg(filt + i);

    const float* e = E + b * Eb;

    const bool interior = (i0 >= 2) && (i0 + TILE <= P - 3) &&
                          (j0 >= 2) && (j0 + TILE <= Q - 3);

    if (interior) {
        for (int r = warp; r < 37; r += 8) {
            const float* src = e + (i0 - 2 + r) * Q + (j0 - 2);
            for (int cc = lane; cc < 37; cc += 32) sE[r][cc] = __ldg(src + cc);
        }
    } else {
        for (int r = warp; r < 37; r += 8) {
            int gi = i0 - 2 + r;
            for (int cc = lane; cc < 37; cc += 32) {
                int gj = j0 - 2 + cc;
                float v = 0.0f;
                if ((unsigned)gi < (unsigned)P && (unsigned)gj < (unsigned)Q)
                    v = __ldg(e + gi * Q + gj);
                sE[r][cc] = v;
            }
        }
    }

    __syncthreads();

    const int col4 = 4 * tx;
    const int RF = ty + 2;   // smem row of i
    const int i  = i0 + ty;

    if (interior) {
        const float gg[6] = {
            KB0,
            0.5f*f[1][0] + KB1,
            0.5f*f[1][1] + KF0 + KB2,
            0.5f*f[1][2] + KF1 + KB3,
            0.5f*f[1][3] + KF2,
            KF3
        };
        float w0[4], w2[4];
        #pragma unroll
        for (int d = 0; d < 4; ++d) { w0[d] = 0.5f*f[0][d]; w2[d] = 0.5f*f[2][d]; }

        float aHx[4] = {0.f,0.f,0.f,0.f};
        float aHy[4] = {0.f,0.f,0.f,0.f};

        // rows i-2..i+3; v[0..7] = sE[RF+t][col4..col4+7], j maps to col4+q+2
        #pragma unroll
        for (int t = -2; t <= 3; ++t) {
            const float* rp = &sE[RF + t][col4];
            float4 A = *(const float4*)rp;
            float4 B = *(const float4*)(rp + 4);
            const float v0=A.x, v1=A.y, v2=A.z, v3=A.w, v4=B.x, v5=B.y, v6=B.z, v7=B.w;

            // Hy 6-tap at col j+1 -> v[q+3]
            const float gc = gg[t + 2];
            aHy[0] += gc * v3; aHy[1] += gc * v4; aHy[2] += gc * v5; aHy[3] += gc * v6;

            if (t >= -1 && t <= 2) {
                // Hy w0 at col j -> v[q+2]; w2 at col j+2 -> v[q+4]
                const float a0 = w0[t + 1], a2 = w2[t + 1];
                aHy[0] += a0 * v2 + a2 * v4;
                aHy[1] += a0 * v3 + a2 * v5;
                aHy[2] += a0 * v4 + a2 * v6;
                aHy[3] += a0 * v5 + a2 * v7;
            }
            if (t == 1) {
                // Hx 6-tap on row i+1, cols j-2..j+3 -> v[q..q+5]
                const float v8 = rp[8];
                const float vv[9] = {v0,v1,v2,v3,v4,v5,v6,v7,v8};
                #pragma unroll
                for (int q = 0; q < 4; ++q) {
                    float s = 0.0f;
                    #pragma unroll
                    for (int k = 0; k < 6; ++k) s += gg[k] * vv[q + k];
                    aHx[q] += s;
                }
            }
            if (t == 0) {
                // Hx w0 on row i, cols j-1..j+2 -> v[q+1..q+4]
                const float vv[8] = {v0,v1,v2,v3,v4,v5,v6,v7};
                #pragma unroll
                for (int q = 0; q < 4; ++q)
                    aHx[q] += w0[0]*vv[q+1] + w0[1]*vv[q+2] + w0[2]*vv[q+3] + w0[3]*vv[q+4];
            }
            if (t == 2) {
                // Hx w2 on row i+2
                const float vv[8] = {v0,v1,v2,v3,v4,v5,v6,v7};
                #pragma unroll
                for (int q = 0; q < 4; ++q)
                    aHx[q] += w2[0]*vv[q+1] + w2[1]*vv[q+2] + w2[2]*vv[q+3] + w2[3]*vv[q+4];
            }
        }

        const float* hxi = Hx + b * Hxb + i * HXC + j0 + col4;
        const float* hyi = Hy + b * Hyb + i * HYC + j0 + col4;
        float* hxo = Hxo + b * Hxob + i * HXC + j0 + col4;
        float* hyo = Hyo + b * Hyob + i * HYC + j0 + col4;
        #pragma unroll
        for (int q = 0; q < 4; ++q) {
            hxo[q] = __ldg(hxi + q) - aHx[q];
            hyo[q] = __ldg(hyi + q) + aHy[q];
        }
    } else {
        const float kf[4] = {KF0, KF1, KF2, KF3};
        const float kb[4] = {KB0, KB1, KB2, KB3};
        #pragma unroll
        for (int q = 0; q < 4; ++q) {
            const int j = j0 + col4 + q;
            const int c = col4 + q + 2;
            // Hx update: i in [0,HXR), j in [0,HXC)
            if (i < HXR && j < HXC) {
                float s = __ldg(Hx + b * Hxb + i * HXC + j);
                if (j >= 1 && j <= Q-3) {
                    float a = 0.0f;
                    #pragma unroll
                    for (int di = 0; di < 3; ++di)
                        #pragma unroll
                        for (int dj = 0; dj < 4; ++dj)
                            a += sE[RF+di][c-1+dj] * f[di][dj];
                    s -= 0.5f * a;
                }
                if (j <= Q-4) {
                    float t = 0.0f;
                    #pragma unroll
                    for (int d = 0; d < 4; ++d) t += sE[RF+1][c+d] * kf[d];
                    s -= t;
                }
                if (j >= 2) {
                    float t = 0.0f;
                    #pragma unroll
                    for (int d = 0; d < 4; ++d) t += sE[RF+1][c-2+d] * kb[d];
                    s -= t;
                }
                Hxo[b * Hxob + i * HXC + j] = s;
            }
            // Hy update: i in [0,HYR), j in [0,HYC)
            if (i < HYR && j < HYC) {
                float s = __ldg(Hy + b * Hyb + i * HYC + j);
                if (i >= 1 && i <= P-3) {
                    float a = 0.0f;
                    #pragma unroll
                    for (int di = 0; di < 4; ++di)
                        #pragma unroll
                        for (int dj = 0; dj < 3; ++dj)
                            a += sE[RF-1+di][c+dj] * f[dj][di];
                    s += 0.5f * a;
                }
                if (i <= P-4) {
                    float t = 0.0f;
                    #pragma unroll
                    for (int d = 0; d < 4; ++d) t += sE[RF+d][c+1] * kf[d];
                    s += t;
                }
                if (i >= 2) {
                    float t = 0.0f;
                    #pragma unroll
                    for (int d = 0; d < 4; ++d) t += sE[RF-2+d][c+1] * kb[d];
                    s += t;
                }
                Hyo[b * Hyob + i * HYC + j] = s;
            }
        }
    }
}

// ---------------------------------------------------------------------------
// Launch: 2 time steps, results written directly into d_out sections.
// d_out layout:
//   E  : BATCH x (2*P) x Q       @ 0
//   Hx : BATCH x (2*HXR) x HXC   @ BATCH*2*P*Q
//   Hy : BATCH x (2*HYR) x HYC   @ BATCH*2*P*Q + BATCH*2*HXR*HXC
// ---------------------------------------------------------------------------
extern "C" void kernel_launch(void* const* d_in, const int* in_sizes, int n_in,
                              void* d_out, int out_size)
{
    const float* E    = (const float*)d_in[0];
    const float* Hx   = (const float*)d_in[1];
    const float* Hy   = (const float*)d_in[2];
    const float* filt = (const float*)d_in[3];
    float* out = (float*)d_out;

    const int E_IN_B  = P * Q;
    const int HX_IN_B = HXR * HXC;
    const int HY_IN_B = HYR * HYC;

    const int E_OUT_B  = 2 * P * Q;
    const int HX_OUT_B = 2 * HXR * HXC;
    const int HY_OUT_B = 2 * HYR * HYC;

    float* En  = out;
    float* Em  = out + P * Q;
    float* Hxn = out + (long long)BATCH * E_OUT_B;
    float* Hxm = Hxn + HXR * HXC;
    float* Hyn = Hxn + (long long)BATCH * HX_OUT_B;
    float* Hym = Hyn + HYR * HYC;

    dim3 blk(8, 32, 1);
    dim3 g(Q / TILE, P / TILE, BATCH);   // (32, 32, 8)

    // Step 1
    amper_tiled<<<g, blk>>>(E, E_IN_B, Hx, HX_IN_B, Hy, HY_IN_B, filt,
                            En, E_OUT_B);
    faraday_tiled<<<g, blk>>>(En, E_OUT_B, Hx, HX_IN_B, Hy, HY_IN_B, filt,
                              Hxn, HX_OUT_B, Hyn, HY_OUT_B);
    // Step 2
    amper_tiled<<<g, blk>>>(En, E_OUT_B, Hxn, HX_OUT_B, Hyn, HY_OUT_B, filt,
                            Em, E_OUT_B);
    faraday_tiled<<<g, blk>>>(Em, E_OUT_B, Hxn, HX_OUT_B, Hyn, HY_OUT_B, filt,
                              Hxm, HX_OUT_B, Hym, HY_OUT_B);
}

// round 11
// speedup vs baseline: 2.1857x; 1.6259x over previous
#include <cuda_runtime.h>

// Problem constants (fixed by setup_inputs)
#define BATCH 8
#define P 1024
#define Q 1024
#define HXR (P-2)   // 1022
#define HXC (Q-1)   // 1023
#define HYR (P-1)   // 1023
#define HYC (Q-2)   // 1022

#define TX 32       // tile cols (blockDim.x)
#define WY 8        // blockDim.y
#define KY 4        // outputs per thread (y)
#define TROWS (WY*KY)   // 32 tile rows
#define NT (TX*WY)      // 256 threads

// KF = 0.5 * [-11/6, 3, -3/2, 1/3] ; KB = -0.5 * reversed
#define KF0 (-11.0f/12.0f)
#define KF1 ( 1.5f)
#define KF2 (-0.75f)
#define KF3 ( 1.0f/6.0f)
#define KB0 (-1.0f/6.0f)
#define KB1 ( 0.75f)
#define KB2 (-1.5f)
#define KB3 ( 11.0f/12.0f)

// ===========================================================================
// amper: E_out[y,x] = E[y,x] + S1(Hy) - S2(Hx)
// Thread (tx,ty): col x = x0+tx, rows y = Y..Y+3, Y = y0 + 4*ty.
// Direct L1 loads; no shared memory, no barrier.
// ===========================================================================
__global__ __launch_bounds__(NT) void amper_ldg(
    const float* __restrict__ E,  int Eb,
    const float* __restrict__ Hx, int Hxb,
    const float* __restrict__ Hy, int Hyb,
    const float* __restrict__ filt,
    float* __restrict__ Eout, int Eob)
{
    const int x0 = blockIdx.x * TX;
    const int y0 = blockIdx.y * TROWS;
    const int b  = blockIdx.z;
    const int tx = threadIdx.x, ty = threadIdx.y;

    float f[3][4];
    #pragma unroll
    for (int i = 0; i < 12; ++i) (&f[0][0])[i] = __ldg(filt + i);

    const float* hy = Hy + b * Hyb;
    const float* hx = Hx + b * Hxb;

    const int Y = y0 + ty * KY;
    const int x = x0 + tx;

    const bool interior = (y0 >= 4) && (y0 + TROWS <= P - 4) &&
                          (x0 >= 2) && (x0 + TX <= Q - 2);

    float acc[KY] = {0.f, 0.f, 0.f, 0.f};

    if (interior) {
        const float hh[8] = {
            KB0, KB1,
            0.5f*f[1][0] + KB2, 0.5f*f[1][1] + KB3,
            0.5f*f[1][2] + KF0, 0.5f*f[1][3] + KF1,
            KF2, KF3
        };
        float w0[4], w2[4];
        #pragma unroll
        for (int d = 0; d < 4; ++d) { w0[d] = 0.5f*f[0][d]; w2[d] = 0.5f*f[2][d]; }

        // ---- S1 (Hy), column-wise, added ----
        {   // col x-2, rows Y-2..Y+4
            float v[KY+3];
            #pragma unroll
            for (int t = 0; t < KY+3; ++t) v[t] = __ldg(hy + (Y-2+t) * HYC + (x-2));
            #pragma unroll
            for (int m = 0; m < KY; ++m)
                #pragma unroll
                for (int d = 0; d < 4; ++d) acc[m] += w0[d]*v[m+d];
        }
        {   // col x-1, rows Y-4..Y+6 (8-tap)
            float v[KY+7];
            #pragma unroll
            for (int t = 0; t < KY+7; ++t) v[t] = __ldg(hy + (Y-4+t) * HYC + (x-1));
            #pragma unroll
            for (int m = 0; m < KY; ++m)
                #pragma unroll
                for (int t = 0; t < 8; ++t) acc[m] += hh[t]*v[m+t];
        }
        {   // col x, rows Y-2..Y+4
            float v[KY+3];
            #pragma unroll
            for (int t = 0; t < KY+3; ++t) v[t] = __ldg(hy + (Y-2+t) * HYC + x);
            #pragma unroll
            for (int m = 0; m < KY; ++m)
                #pragma unroll
                for (int d = 0; d < 4; ++d) acc[m] += w2[d]*v[m+d];
        }

        // ---- S2 (Hx), row-wise, subtracted ----
        {   // row Y-2: w0 over cols x-2..x+1 (output m=0 only)
            #pragma unroll
            for (int d = 0; d < 4; ++d)
                acc[0] -= w0[d] * __ldg(hx + (Y-2) * HXC + (x-2+d));
        }
        #pragma unroll
        for (int ro = -1; ro <= 2; ++ro) {   // rows Y-1..Y+2, cols x-4..x+3
            float v[8];
            #pragma unroll
            for (int t = 0; t < 8; ++t) v[t] = __ldg(hx + (Y+ro) * HXC + (x-4+t));
            const int m8 = ro + 1;
            #pragma unroll
            for (int t = 0; t < 8; ++t) acc[m8] -= hh[t]*v[t];
            if (ro <= 1) {
                #pragma unroll
                for (int d = 0; d < 4; ++d) acc[ro+2] -= w0[d]*v[d+2];
            }
            if (ro >= 0) {
                #pragma unroll
                for (int d = 0; d < 4; ++d) acc[ro] -= w2[d]*v[d+2];
            }
        }
        {   // row Y+3: w2 over cols x-2..x+1 (output m=3 only)
            #pragma unroll
            for (int d = 0; d < 4; ++d)
                acc[3] -= w2[d] * __ldg(hx + (Y+3) * HXC + (x-2+d));
        }
    } else {
        const float kf[4] = {KF0, KF1, KF2, KF3};
        const float kb[4] = {KB0, KB1, KB2, KB3};
        #pragma unroll
        for (int m = 0; m < KY; ++m) {
            const int y = Y + m;
            float s = 0.0f;
            // S1
            if (y >= 2 && y <= P-3 && x >= 2 && x <= Q-3) {
                float a = 0.0f;
                #pragma unroll
                for (int di = 0; di < 4; ++di)
                    #pragma unroll
                    for (int dj = 0; dj < 3; ++dj)
                        a += __ldg(hy + (y-2+di) * HYC + (x-2+dj)) * f[dj][di];
                s += 0.5f * a;
            }
            if (x >= 1 && x <= Q-2) {
                if (y <= P-5) {
                    float t = 0.0f;
                    #pragma unroll
                    for (int d = 0; d < 4; ++d) t += __ldg(hy + (y+d) * HYC + (x-1)) * kf[d];
                    s += t;
                }
                if (y >= 4) {
                    float t = 0.0f;
                    #pragma unroll
                    for (int d = 0; d < 4; ++d) t += __ldg(hy + (y-4+d) * HYC + (x-1)) * kb[d];
                    s += t;
                }
            }
            // S2
            if (y >= 2 && y <= P-3 && x >= 2 && x <= Q-3) {
                float a = 0.0f;
                #pragma unroll
                for (int di = 0; di < 3; ++di)
                    #pragma unroll
                    for (int dj = 0; dj < 4; ++dj)
                        a += __ldg(hx + (y-2+di) * HXC + (x-2+dj)) * f[di][dj];
                s -= 0.5f * a;
            }
            if (y >= 1 && y <= P-2) {
                if (x <= Q-5) {
                    float t = 0.0f;
                    #pragma unroll
                    for (int d = 0; d < 4; ++d) t += __ldg(hx + (y-1) * HXC + (x+d)) * kf[d];
                    s -= t;
                }
                if (x >= 4) {
                    float t = 0.0f;
                    #pragma unroll
                    for (int d = 0; d < 4; ++d) t += __ldg(hx + (y-1) * HXC + (x-4+d)) * kb[d];
                    s -= t;
                }
            }
            acc[m] = s;
        }
    }

    const float* e = E + b * Eb;
    float* eo = Eout + b * Eob;
    #pragma unroll
    for (int m = 0; m < KY; ++m)
        eo[(Y+m) * Q + x] = __ldg(e + (Y+m) * Q + x) + acc[m];
}

// ===========================================================================
// faraday: Hx_out[i,j] = Hx[i,j] - S3(E);  Hy_out[i,j] = Hy[i,j] + S4(E)
// Thread (tx,ty): col j = j0+tx, rows i = I..I+3, I = i0 + 4*ty.
// ===========================================================================
__global__ __launch_bounds__(NT) void faraday_ldg(
    const float* __restrict__ E,  int Eb,
    const float* __restrict__ Hx, int Hxb,
    const float* __restrict__ Hy, int Hyb,
    const float* __restrict__ filt,
    float* __restrict__ Hxo, int Hxob,
    float* __restrict__ Hyo, int Hyob)
{
    const int j0 = blockIdx.x * TX;
    const int i0 = blockIdx.y * TROWS;
    const int b  = blockIdx.z;
    const int tx = threadIdx.x, ty = threadIdx.y;

    float f[3][4];
    #pragma unroll
    for (int i = 0; i < 12; ++i) (&f[0][0])[i] = __ldg(filt + i);

    const float* e = E + b * Eb;

    const int I = i0 + ty * KY;
    const int j = j0 + tx;

    const bool interior = (i0 >= 2) && (i0 + TROWS <= P - 3) &&
                          (j0 >= 2) && (j0 + TX <= Q - 3);

    if (interior) {
        const float gg[6] = {
            KB0,
            0.5f*f[1][0] + KB1,
            0.5f*f[1][1] + KF0 + KB2,
            0.5f*f[1][2] + KF1 + KB3,
            0.5f*f[1][3] + KF2,
            KF3
        };
        float w0[4], w2[4];
        #pragma unroll
        for (int d = 0; d < 4; ++d) { w0[d] = 0.5f*f[0][d]; w2[d] = 0.5f*f[2][d]; }

        float aHx[KY] = {0.f,0.f,0.f,0.f};
        float aHy[KY] = {0.f,0.f,0.f,0.f};

        {   // col j-2: rows I..I+5
            float v[KY+2];
            #pragma unroll
            for (int t = 0; t < KY+2; ++t) v[t] = __ldg(e + (I+t) * Q + (j-2));
            #pragma unroll
            for (int m = 0; m < KY; ++m) aHx[m] += gg[0]*v[m+1];
        }
        {   // col j-1: rows I..I+5
            float v[KY+2];
            #pragma unroll
            for (int t = 0; t < KY+2; ++t) v[t] = __ldg(e + (I+t) * Q + (j-1));
            #pragma unroll
            for (int m = 0; m < KY; ++m)
                aHx[m] += gg[1]*v[m+1] + w0[0]*v[m] + w2[0]*v[m+2];
        }
        {   // col j: rows I-1..I+5
            float v[KY+3];
            #pragma unroll
            for (int t = 0; t < KY+3; ++t) v[t] = __ldg(e + (I-1+t) * Q + j);
            #pragma unroll
            for (int m = 0; m < KY; ++m) {
                aHx[m] += gg[2]*v[m+2] + w0[1]*v[m+1] + w2[1]*v[m+3];
                #pragma unroll
                for (int d = 0; d < 4; ++d) aHy[m] += w0[d]*v[m+d];
            }
        }
        {   // col j+1: rows I-2..I+6
            float v[KY+5];
            #pragma unroll
            for (int t = 0; t < KY+5; ++t) v[t] = __ldg(e + (I-2+t) * Q + (j+1));
            #pragma unroll
            for (int m = 0; m < KY; ++m) {
                aHx[m] += gg[3]*v[m+3] + w0[2]*v[m+2] + w2[2]*v[m+4];
                #pragma unroll
                for (int t = 0; t < 6; ++t) aHy[m] += gg[t]*v[m+t];
            }
        }
        {   // col j+2: rows I-1..I+5
            float v[KY+3];
            #pragma unroll
            for (int t = 0; t < KY+3; ++t) v[t] = __ldg(e + (I-1+t) * Q + (j+2));
            #pragma unroll
            for (int m = 0; m < KY; ++m) {
                aHx[m] += gg[4]*v[m+2] + w0[3]*v[m+1] + w2[3]*v[m+3];
                #pragma unroll
                for (int d = 0; d < 4; ++d) aHy[m] += w2[d]*v[m+d];
            }
        }
        {   // col j+3: rows I..I+5
            float v[KY+2];
            #pragma unroll
            for (int t = 0; t < KY+2; ++t) v[t] = __ldg(e + (I+t) * Q + (j+3));
            #pragma unroll
            for (int m = 0; m < KY; ++m) aHx[m] += gg[5]*v[m+1];
        }

        const float* hxi = Hx + b * Hxb;
        const float* hyi = Hy + b * Hyb;
        float* hxo = Hxo + b * Hxob;
        float* hyo = Hyo + b * Hyob;
        #pragma unroll
        for (int m = 0; m < KY; ++m) {
            const int i = I + m;
            hxo[i * HXC + j] = __ldg(hxi + i * HXC + j) - aHx[m];
            hyo[i * HYC + j] = __ldg(hyi + i * HYC + j) + aHy[m];
        }
    } else {
        const float kf[4] = {KF0, KF1, KF2, KF3};
        const float kb[4] = {KB0, KB1, KB2, KB3};
        #pragma unroll
        for (int m = 0; m < KY; ++m) {
            const int i = I + m;
            // Hx update: i in [0,HXR), j in [0,HXC)
            if (i < HXR && j < HXC) {
                float s = __ldg(Hx + b * Hxb + i * HXC + j);
                if (j >= 1 && j <= Q-3) {
                    float a = 0.0f;
                    #pragma unroll
                    for (int di = 0; di < 3; ++di)
                        #pragma unroll
                        for (int dj = 0; dj < 4; ++dj)
                            a += __ldg(e + (i+di) * Q + (j-1+dj)) * f[di][dj];
                    s -= 0.5f * a;
                }
                if (j <= Q-4) {
                    float t = 0.0f;
                    #pragma unroll
                    for (int d = 0; d < 4; ++d) t += __ldg(e + (i+1) * Q + (j+d)) * kf[d];
                    s -= t;
                }
                if (j >= 2) {
                    float t = 0.0f;
                    #pragma unroll
                    for (int d = 0; d < 4; ++d) t += __ldg(e + (i+1) * Q + (j-2+d)) * kb[d];
                    s -= t;
                }
                Hxo[b * Hxob + i * HXC + j] = s;
            }
            // Hy update: i in [0,HYR), j in [0,HYC)
            if (i < HYR && j < HYC) {
                float s = __ldg(Hy + b * Hyb + i * HYC + j);
                if (i >= 1 && i <= P-3) {
                    float a = 0.0f;
                    #pragma unroll
                    for (int di = 0; di < 4; ++di)
                        #pragma unroll
                        for (int dj = 0; dj < 3; ++dj)
                            a += __ldg(e + (i-1+di) * Q + (j+dj)) * f[dj][di];
                    s += 0.5f * a;
                }
                if (i <= P-4) {
                    float t = 0.0f;
                    #pragma unroll
                    for (int d = 0; d < 4; ++d) t += __ldg(e + (i+d) * Q + (j+1)) * kf[d];
                    s += t;
                }
                if (i >= 2) {
                    float t = 0.0f;
                    #pragma unroll
                    for (int d = 0; d < 4; ++d) t += __ldg(e + (i-2+d) * Q + (j+1)) * kb[d];
                    s += t;
                }
                Hyo[b * Hyob + i * HYC + j] = s;
            }
        }
    }
}

// ---------------------------------------------------------------------------
// Launch: 2 time steps, results written directly into d_out sections.
// d_out layout:
//   E  : BATCH x (2*P) x Q       @ 0
//   Hx : BATCH x (2*HXR) x HXC   @ BATCH*2*P*Q
//   Hy : BATCH x (2*HYR) x HYC   @ BATCH*2*P*Q + BATCH*2*HXR*HXC
// ---------------------------------------------------------------------------
extern "C" void kernel_launch(void* const* d_in, const int* in_sizes, int n_in,
                              void* d_out, int out_size)
{
    const float* E    = (const float*)d_in[0];
    const float* Hx   = (const float*)d_in[1];
    const float* Hy   = (const float*)d_in[2];
    const float* filt = (const float*)d_in[3];
    float* out = (float*)d_out;

    const int E_IN_B  = P * Q;
    const int HX_IN_B = HXR * HXC;
    const int HY_IN_B = HYR * HYC;

    const int E_OUT_B  = 2 * P * Q;
    const int HX_OUT_B = 2 * HXR * HXC;
    const int HY_OUT_B = 2 * HYR * HYC;

    float* En  = out;
    float* Em  = out + P * Q;
    float* Hxn = out + (long long)BATCH * E_OUT_B;
    float* Hxm = Hxn + HXR * HXC;
    float* Hyn = Hxn + (long long)BATCH * HX_OUT_B;
    float* Hym = Hyn + HYR * HYC;

    dim3 blk(TX, WY, 1);
    dim3 g(Q / TX, P / TROWS, BATCH);   // (32, 32, 8)

    // Step 1
    amper_ldg<<<g, blk>>>(E, E_IN_B, Hx, HX_IN_B, Hy, HY_IN_B, filt,
                          En, E_OUT_B);
    faraday_ldg<<<g, blk>>>(En, E_OUT_B, Hx, HX_IN_B, Hy, HY_IN_B, filt,
                            Hxn, HX_OUT_B, Hyn, HY_OUT_B);
    // Step 2
    amper_ldg<<<g, blk>>>(En, E_OUT_B, Hxn, HX_OUT_B, Hyn, HY_OUT_B, filt,
                          Em, E_OUT_B);
    faraday_ldg<<<g, blk>>>(Em, E_OUT_B, Hxn, HX_OUT_B, Hyn, HY_OUT_B, filt,
                            Hxm, HX_OUT_B, Hym, HY_OUT_B);
}

// round 12
// speedup vs baseline: 2.1916x; 1.0027x over previous
#include <cuda_runtime.h>

// Problem constants (fixed by setup_inputs)
#define BATCH 8
#define P 1024
#define Q 1024
#define HXR (P-2)   // 1022
#define HXC (Q-1)   // 1023
#define HYR (P-1)   // 1023
#define HYC (Q-2)   // 1022

#define TX 32       // tile cols (blockDim.x)
#define WY 8        // blockDim.y
#define KY 4        // outputs per thread (y)
#define TROWS (WY*KY)   // 32 tile rows
#define NT (TX*WY)      // 256 threads

// KF = 0.5 * [-11/6, 3, -3/2, 1/3] ; KB = -0.5 * reversed
#define KF0 (-11.0f/12.0f)
#define KF1 ( 1.5f)
#define KF2 (-0.75f)
#define KF3 ( 1.0f/6.0f)
#define KB0 (-1.0f/6.0f)
#define KB1 ( 0.75f)
#define KB2 (-1.5f)
#define KB3 ( 11.0f/12.0f)

// ===========================================================================
// amper: E_out[y,x] = E[y,x] + S1(Hy) - S2(Hx)
// Thread (tx,ty): col x = x0+tx, rows y = Y..Y+3, Y = y0 + 4*ty.
// Direct L1 loads; no shared memory, no barrier.
// ===========================================================================
__global__ __launch_bounds__(NT) void amper_ldg(
    const float* __restrict__ E,  int Eb,
    const float* __restrict__ Hx, int Hxb,
    const float* __restrict__ Hy, int Hyb,
    const float* __restrict__ filt,
    float* __restrict__ Eout, int Eob)
{
    const int x0 = blockIdx.x * TX;
    const int y0 = blockIdx.y * TROWS;
    const int b  = blockIdx.z;
    const int tx = threadIdx.x, ty = threadIdx.y;

    float f[3][4];
    #pragma unroll
    for (int i = 0; i < 12; ++i) (&f[0][0])[i] = __ldg(filt + i);

    const float* hy = Hy + b * Hyb;
    const float* hx = Hx + b * Hxb;

    const int Y = y0 + ty * KY;
    const int x = x0 + tx;

    const bool interior = (y0 >= 4) && (y0 + TROWS <= P - 4) &&
                          (x0 >= 2) && (x0 + TX <= Q - 2);

    float acc[KY] = {0.f, 0.f, 0.f, 0.f};

    if (interior) {
        const float hh[8] = {
            KB0, KB1,
            0.5f*f[1][0] + KB2, 0.5f*f[1][1] + KB3,
            0.5f*f[1][2] + KF0, 0.5f*f[1][3] + KF1,
            KF2, KF3
        };
        float w0[4], w2[4];
        #pragma unroll
        for (int d = 0; d < 4; ++d) { w0[d] = 0.5f*f[0][d]; w2[d] = 0.5f*f[2][d]; }

        // ---- S1 (Hy), column-wise, added ----
        {   // col x-2, rows Y-2..Y+4
            float v[KY+3];
            #pragma unroll
            for (int t = 0; t < KY+3; ++t) v[t] = __ldg(hy + (Y-2+t) * HYC + (x-2));
            #pragma unroll
            for (int m = 0; m < KY; ++m)
                #pragma unroll
                for (int d = 0; d < 4; ++d) acc[m] += w0[d]*v[m+d];
        }
        {   // col x-1, rows Y-4..Y+6 (8-tap)
            float v[KY+7];
            #pragma unroll
            for (int t = 0; t < KY+7; ++t) v[t] = __ldg(hy + (Y-4+t) * HYC + (x-1));
            #pragma unroll
            for (int m = 0; m < KY; ++m)
                #pragma unroll
                for (int t = 0; t < 8; ++t) acc[m] += hh[t]*v[m+t];
        }
        {   // col x, rows Y-2..Y+4
            float v[KY+3];
            #pragma unroll
            for (int t = 0; t < KY+3; ++t) v[t] = __ldg(hy + (Y-2+t) * HYC + x);
            #pragma unroll
            for (int m = 0; m < KY; ++m)
                #pragma unroll
                for (int d = 0; d < 4; ++d) acc[m] += w2[d]*v[m+d];
        }

        // ---- S2 (Hx), row-wise, subtracted ----
        {   // row Y-2: w0 over cols x-2..x+1 (output m=0 only)
            #pragma unroll
            for (int d = 0; d < 4; ++d)
                acc[0] -= w0[d] * __ldg(hx + (Y-2) * HXC + (x-2+d));
        }
        #pragma unroll
        for (int ro = -1; ro <= 2; ++ro) {   // rows Y-1..Y+2, cols x-4..x+3
            float v[8];
            #pragma unroll
            for (int t = 0; t < 8; ++t) v[t] = __ldg(hx + (Y+ro) * HXC + (x-4+t));
            const int m8 = ro + 1;
            #pragma unroll
            for (int t = 0; t < 8; ++t) acc[m8] -= hh[t]*v[t];
            if (ro <= 1) {
                #pragma unroll
                for (int d = 0; d < 4; ++d) acc[ro+2] -= w0[d]*v[d+2];
            }
            if (ro >= 0) {
                #pragma unroll
                for (int d = 0; d < 4; ++d) acc[ro] -= w2[d]*v[d+2];
            }
        }
        {   // row Y+3: w2 over cols x-2..x+1 (output m=3 only)
            #pragma unroll
            for (int d = 0; d < 4; ++d)
                acc[3] -= w2[d] * __ldg(hx + (Y+3) * HXC + (x-2+d));
        }
    } else {
        const float kf[4] = {KF0, KF1, KF2, KF3};
        const float kb[4] = {KB0, KB1, KB2, KB3};
        #pragma unroll
        for (int m = 0; m < KY; ++m) {
            const int y = Y + m;
            float s = 0.0f;
            // S1
            if (y >= 2 && y <= P-3 && x >= 2 && x <= Q-3) {
                float a = 0.0f;
                #pragma unroll
                for (int di = 0; di < 4; ++di)
                    #pragma unroll
                    for (int dj = 0; dj < 3; ++dj)
                        a += __ldg(hy + (y-2+di) * HYC + (x-2+dj)) * f[dj][di];
                s += 0.5f * a;
            }
            if (x >= 1 && x <= Q-2) {
                if (y <= P-5) {
                    float t = 0.0f;
                    #pragma unroll
                    for (int d = 0; d < 4; ++d) t += __ldg(hy + (y+d) * HYC + (x-1)) * kf[d];
                    s += t;
                }
                if (y >= 4) {
                    float t = 0.0f;
                    #pragma unroll
                    for (int d = 0; d < 4; ++d) t += __ldg(hy + (y-4+d) * HYC + (x-1)) * kb[d];
                    s += t;
                }
            }
            // S2
            if (y >= 2 && y <= P-3 && x >= 2 && x <= Q-3) {
                float a = 0.0f;
                #pragma unroll
                for (int di = 0; di < 3; ++di)
                    #pragma unroll
                    for (int dj = 0; dj < 4; ++dj)
                        a += __ldg(hx + (y-2+di) * HXC + (x-2+dj)) * f[di][dj];
                s -= 0.5f * a;
            }
            if (y >= 1 && y <= P-2) {
                if (x <= Q-5) {
                    float t = 0.0f;
                    #pragma unroll
                    for (int d = 0; d < 4; ++d) t += __ldg(hx + (y-1) * HXC + (x+d)) * kf[d];
                    s -= t;
                }
                if (x >= 4) {
                    float t = 0.0f;
                    #pragma unroll
                    for (int d = 0; d < 4; ++d) t += __ldg(hx + (y-1) * HXC + (x-4+d)) * kb[d];
                    s -= t;
                }
            }
            acc[m] = s;
        }
    }

    const float* e = E + b * Eb;
    float* eo = Eout + b * Eob;
    #pragma unroll
    for (int m = 0; m < KY; ++m)
        eo[(Y+m) * Q + x] = __ldg(e + (Y+m) * Q + x) + acc[m];
}

// ===========================================================================
// faraday: Hx_out[i,j] = Hx[i,j] - S3(E);  Hy_out[i,j] = Hy[i,j] + S4(E)
// Thread (tx,ty): col j = j0+tx, rows i = I..I+3, I = i0 + 4*ty.
// ===========================================================================
__global__ __launch_bounds__(NT) void faraday_ldg(
    const float* __restrict__ E,  int Eb,
    const float* __restrict__ Hx, int Hxb,
    const float* __restrict__ Hy, int Hyb,
    const float* __restrict__ filt,
    float* __restrict__ Hxo, int Hxob,
    float* __restrict__ Hyo, int Hyob)
{
    const int j0 = blockIdx.x * TX;
    const int i0 = blockIdx.y * TROWS;
    const int b  = blockIdx.z;
    const int tx = threadIdx.x, ty = threadIdx.y;

    float f[3][4];
    #pragma unroll
    for (int i = 0; i < 12; ++i) (&f[0][0])[i] = __ldg(filt + i);

    const float* e = E + b * Eb;

    const int I = i0 + ty * KY;
    const int j = j0 + tx;

    const bool interior = (i0 >= 2) && (i0 + TROWS <= P - 3) &&
                          (j0 >= 2) && (j0 + TX <= Q - 3);

    if (interior) {
        const float gg[6] = {
            KB0,
            0.5f*f[1][0] + KB1,
            0.5f*f[1][1] + KF0 + KB2,
            0.5f*f[1][2] + KF1 + KB3,
            0.5f*f[1][3] + KF2,
            KF3
        };
        float w0[4], w2[4];
        #pragma unroll
        for (int d = 0; d < 4; ++d) { w0[d] = 0.5f*f[0][d]; w2[d] = 0.5f*f[2][d]; }

        float aHx[KY] = {0.f,0.f,0.f,0.f};
        float aHy[KY] = {0.f,0.f,0.f,0.f};

        {   // col j-2: rows I..I+5
            float v[KY+2];
            #pragma unroll
            for (int t = 0; t < KY+2; ++t) v[t] = __ldg(e + (I+t) * Q + (j-2));
            #pragma unroll
            for (int m = 0; m < KY; ++m) aHx[m] += gg[0]*v[m+1];
        }
        {   // col j-1: rows I..I+5
            float v[KY+2];
            #pragma unroll
            for (int t = 0; t < KY+2; ++t) v[t] = __ldg(e + (I+t) * Q + (j-1));
            #pragma unroll
            for (int m = 0; m < KY; ++m)
                aHx[m] += gg[1]*v[m+1] + w0[0]*v[m] + w2[0]*v[m+2];
        }
        {   // col j: rows I-1..I+5
            float v[KY+3];
            #pragma unroll
            for (int t = 0; t < KY+3; ++t) v[t] = __ldg(e + (I-1+t) * Q + j);
            #pragma unroll
            for (int m = 0; m < KY; ++m) {
                aHx[m] += gg[2]*v[m+2] + w0[1]*v[m+1] + w2[1]*v[m+3];
                #pragma unroll
                for (int d = 0; d < 4; ++d) aHy[m] += w0[d]*v[m+d];
            }
        }
        {   // col j+1: rows I-2..I+6
            float v[KY+5];
            #pragma unroll
            for (int t = 0; t < KY+5; ++t) v[t] = __ldg(e + (I-2+t) * Q + (j+1));
            #pragma unroll
            for (int m = 0; m < KY; ++m) {
                aHx[m] += gg[3]*v[m+3] + w0[2]*v[m+2] + w2[2]*v[m+4];
                #pragma unroll
                for (int t = 0; t < 6; ++t) aHy[m] += gg[t]*v[m+t];
            }
        }
        {   // col j+2: rows I-1..I+5
            float v[KY+3];
            #pragma unroll
            for (int t = 0; t < KY+3; ++t) v[t] = __ldg(e + (I-1+t) * Q + (j+2));
            #pragma unroll
            for (int m = 0; m < KY; ++m) {
                aHx[m] += gg[4]*v[m+2] + w0[3]*v[m+1] + w2[3]*v[m+3];
                #pragma unroll
                for (int d = 0; d < 4; ++d) aHy[m] += w2[d]*v[m+d];
            }
        }
        {   // col j+3: rows I..I+5
            float v[KY+2];
            #pragma unroll
            for (int t = 0; t < KY+2; ++t) v[t] = __ldg(e + (I+t) * Q + (j+3));
            #pragma unroll
            for (int m = 0; m < KY; ++m) aHx[m] += gg[5]*v[m+1];
        }

        const float* hxi = Hx + b * Hxb;
        const float* hyi = Hy + b * Hyb;
        float* hxo = Hxo + b * Hxob;
        float* hyo = Hyo + b * Hyob;
        #pragma unroll
        for (int m = 0; m < KY; ++m) {
            const int i = I + m;
            hxo[i * HXC + j] = __ldg(hxi + i * HXC + j) - aHx[m];
            hyo[i * HYC + j] = __ldg(hyi + i * HYC + j) + aHy[m];
        }
    } else {
        const float kf[4] = {KF0, KF1, KF2, KF3};
        const float kb[4] = {KB0, KB1, KB2, KB3};
        #pragma unroll
        for (int m = 0; m < KY; ++m) {
            const int i = I + m;
            // Hx update: i in [0,HXR), j in [0,HXC)
            if (i < HXR && j < HXC) {
                float s = __ldg(Hx + b * Hxb + i * HXC + j);
                if (j >= 1 && j <= Q-3) {
                    float a = 0.0f;
                    #pragma unroll
                    for (int di = 0; di < 3; ++di)
                        #pragma unroll
                        for (int dj = 0; dj < 4; ++dj)
                            a += __ldg(e + (i+di) * Q + (j-1+dj)) * f[di][dj];
                    s -= 0.5f * a;
                }
                if (j <= Q-4) {
                    float t = 0.0f;
                    #pragma unroll
                    for (int d = 0; d < 4; ++d) t += __ldg(e + (i+1) * Q + (j+d)) * kf[d];
                    s -= t;
                }
                if (j >= 2) {
                    float t = 0.0f;
                    #pragma unroll
                    for (int d = 0; d < 4; ++d) t += __ldg(e + (i+1) * Q + (j-2+d)) * kb[d];
                    s -= t;
                }
                Hxo[b * Hxob + i * HXC + j] = s;
            }
            // Hy update: i in [0,HYR), j in [0,HYC)
            if (i < HYR && j < HYC) {
                float s = __ldg(Hy + b * Hyb + i * HYC + j);
                if (i >= 1 && i <= P-3) {
                    float a = 0.0f;
                    #pragma unroll
                    for (int di = 0; di < 4; ++di)
                        #pragma unroll
                        for (int dj = 0; dj < 3; ++dj)
                            a += __ldg(e + (i-1+di) * Q + (j+dj)) * f[dj][di];
                    s += 0.5f * a;
                }
                if (i <= P-4) {
                    float t = 0.0f;
                    #pragma unroll
                    for (int d = 0; d < 4; ++d) t += __ldg(e + (i+d) * Q + (j+1)) * kf[d];
                    s += t;
                }
                if (i >= 2) {
                    float t = 0.0f;
                    #pragma unroll
                    for (int d = 0; d < 4; ++d) t += __ldg(e + (i-2+d) * Q + (j+1)) * kb[d];
                    s += t;
                }
                Hyo[b * Hyob + i * HYC + j] = s;
            }
        }
    }
}

// ---------------------------------------------------------------------------
// Launch: 2 time steps, results written directly into d_out sections.
// d_out layout:
//   E  : BATCH x (2*P) x Q       @ 0
//   Hx : BATCH x (2*HXR) x HXC   @ BATCH*2*P*Q
//   Hy : BATCH x (2*HYR) x HYC   @ BATCH*2*P*Q + BATCH*2*HXR*HXC
// ---------------------------------------------------------------------------
extern "C" void kernel_launch(void* const* d_in, const int* in_sizes, int n_in,
                              void* d_out, int out_size)
{
    const float* E    = (const float*)d_in[0];
    const float* Hx   = (const float*)d_in[1];
    const float* Hy   = (const float*)d_in[2];
    const float* filt = (const float*)d_in[3];
    float* out = (float*)d_out;

    const int E_IN_B  = P * Q;
    const int HX_IN_B = HXR * HXC;
    const int HY_IN_B = HYR * HYC;

    const int E_OUT_B  = 2 * P * Q;
    const int HX_OUT_B = 2 * HXR * HXC;
    const int HY_OUT_B = 2 * HYR * HYC;

    float* En  = out;
    float* Em  = out + P * Q;
    float* Hxn = out + (long long)BATCH * E_OUT_B;
    float* Hxm = Hxn + HXR * HXC;
    float* Hyn = Hxn + (long long)BATCH * HX_OUT_B;
    float* Hym = Hyn + HYR * HYC;

    dim3 blk(TX, WY, 1);
    dim3 g(Q / TX, P / TROWS, BATCH);   // (32, 32, 8)

    // Step 1
    amper_ldg<<<g, blk>>>(E, E_IN_B, Hx, HX_IN_B, Hy, HY_IN_B, filt,
                          En, E_OUT_B);
    faraday_ldg<<<g, blk>>>(En, E_OUT_B, Hx, HX_IN_B, Hy, HY_IN_B, filt,
                            Hxn, HX_OUT_B, Hyn, HY_OUT_B);
    // Step 2
    amper_ldg<<<g, blk>>>(En, E_OUT_B, Hxn, HX_OUT_B, Hyn, HY_OUT_B, filt,
                          Em, E_OUT_B);
    faraday_ldg<<<g, blk>>>(Em, E_OUT_B, Hxn, HX_OUT_B, Hyn, HY_OUT_B, filt,
                            Hxm, HX_OUT_B, Hym, HY_OUT_B);
}

// round 13
// speedup vs baseline: 2.1927x; 1.0005x over previous
#include <cuda_runtime.h>

// Problem constants (fixed by setup_inputs)
#define BATCH 8
#define P 1024
#define Q 1024
#define HXR (P-2)   // 1022
#define HXC (Q-1)   // 1023
#define HYR (P-1)   // 1023
#define HYC (Q-2)   // 1022

#define TX 32       // tile cols (blockDim.x)
#define WY 8        // blockDim.y
#define KY 4        // outputs per thread (y)
#define TROWS (WY*KY)   // 32 tile rows
#define NT (TX*WY)      // 256 threads

// KF = 0.5 * [-11/6, 3, -3/2, 1/3] ; KB = -0.5 * reversed
#define KF0 (-11.0f/12.0f)
#define KF1 ( 1.5f)
#define KF2 (-0.75f)
#define KF3 ( 1.0f/6.0f)
#define KB0 (-1.0f/6.0f)
#define KB1 ( 0.75f)
#define KB2 (-1.5f)
#define KB3 ( 11.0f/12.0f)

// ===========================================================================
// amper: E_out[y,x] = E[y,x] + S1(Hy) - S2(Hx)
// Thread (tx,ty): col x = x0+tx, rows y = Y..Y+3, Y = y0 + 4*ty.
// Direct L1 loads; no shared memory, no barrier.
// ===========================================================================
__global__ __launch_bounds__(NT) void amper_ldg(
    const float* __restrict__ E,  int Eb,
    const float* __restrict__ Hx, int Hxb,
    const float* __restrict__ Hy, int Hyb,
    const float* __restrict__ filt,
    float* __restrict__ Eout, int Eob)
{
    const int x0 = blockIdx.x * TX;
    const int y0 = blockIdx.y * TROWS;
    const int b  = blockIdx.z;
    const int tx = threadIdx.x, ty = threadIdx.y;

    float f[3][4];
    #pragma unroll
    for (int i = 0; i < 12; ++i) (&f[0][0])[i] = __ldg(filt + i);

    const float* hy = Hy + b * Hyb;
    const float* hx = Hx + b * Hxb;

    const int Y = y0 + ty * KY;
    const int x = x0 + tx;

    const bool interior = (y0 >= 4) && (y0 + TROWS <= P - 4) &&
                          (x0 >= 2) && (x0 + TX <= Q - 2);

    float acc[KY] = {0.f, 0.f, 0.f, 0.f};

    if (interior) {
        const float hh[8] = {
            KB0, KB1,
            0.5f*f[1][0] + KB2, 0.5f*f[1][1] + KB3,
            0.5f*f[1][2] + KF0, 0.5f*f[1][3] + KF1,
            KF2, KF3
        };
        float w0[4], w2[4];
        #pragma unroll
        for (int d = 0; d < 4; ++d) { w0[d] = 0.5f*f[0][d]; w2[d] = 0.5f*f[2][d]; }

        // ---- S1 (Hy), column-wise, added ----
        {   // col x-2, rows Y-2..Y+4
            float v[KY+3];
            #pragma unroll
            for (int t = 0; t < KY+3; ++t) v[t] = __ldg(hy + (Y-2+t) * HYC + (x-2));
            #pragma unroll
            for (int m = 0; m < KY; ++m)
                #pragma unroll
                for (int d = 0; d < 4; ++d) acc[m] += w0[d]*v[m+d];
        }
        {   // col x-1, rows Y-4..Y+6 (8-tap)
            float v[KY+7];
            #pragma unroll
            for (int t = 0; t < KY+7; ++t) v[t] = __ldg(hy + (Y-4+t) * HYC + (x-1));
            #pragma unroll
            for (int m = 0; m < KY; ++m)
                #pragma unroll
                for (int t = 0; t < 8; ++t) acc[m] += hh[t]*v[m+t];
        }
        {   // col x, rows Y-2..Y+4
            float v[KY+3];
            #pragma unroll
            for (int t = 0; t < KY+3; ++t) v[t] = __ldg(hy + (Y-2+t) * HYC + x);
            #pragma unroll
            for (int m = 0; m < KY; ++m)
                #pragma unroll
                for (int d = 0; d < 4; ++d) acc[m] += w2[d]*v[m+d];
        }

        // ---- S2 (Hx), row-wise, subtracted ----
        {   // row Y-2: w0 over cols x-2..x+1 (output m=0 only)
            #pragma unroll
            for (int d = 0; d < 4; ++d)
                acc[0] -= w0[d] * __ldg(hx + (Y-2) * HXC + (x-2+d));
        }
        #pragma unroll
        for (int ro = -1; ro <= 2; ++ro) {   // rows Y-1..Y+2, cols x-4..x+3
            float v[8];
            #pragma unroll
            for (int t = 0; t < 8; ++t) v[t] = __ldg(hx + (Y+ro) * HXC + (x-4+t));
            const int m8 = ro + 1;
            #pragma unroll
            for (int t = 0; t < 8; ++t) acc[m8] -= hh[t]*v[t];
            if (ro <= 1) {
                #pragma unroll
                for (int d = 0; d < 4; ++d) acc[ro+2] -= w0[d]*v[d+2];
            }
            if (ro >= 0) {
                #pragma unroll
                for (int d = 0; d < 4; ++d) acc[ro] -= w2[d]*v[d+2];
            }
        }
        {   // row Y+3: w2 over cols x-2..x+1 (output m=3 only)
            #pragma unroll
            for (int d = 0; d < 4; ++d)
                acc[3] -= w2[d] * __ldg(hx + (Y+3) * HXC + (x-2+d));
        }
    } else {
        const float kf[4] = {KF0, KF1, KF2, KF3};
        const float kb[4] = {KB0, KB1, KB2, KB3};
        #pragma unroll
        for (int m = 0; m < KY; ++m) {
            const int y = Y + m;
            float s = 0.0f;
            // S1
            if (y >= 2 && y <= P-3 && x >= 2 && x <= Q-3) {
                float a = 0.0f;
                #pragma unroll
                for (int di = 0; di < 4; ++di)
                    #pragma unroll
                    for (int dj = 0; dj < 3; ++dj)
                        a += __ldg(hy + (y-2+di) * HYC + (x-2+dj)) * f[dj][di];
                s += 0.5f * a;
            }
            if (x >= 1 && x <= Q-2) {
                if (y <= P-5) {
                    float t = 0.0f;
                    #pragma unroll
                    for (int d = 0; d < 4; ++d) t += __ldg(hy + (y+d) * HYC + (x-1)) * kf[d];
                    s += t;
                }
                if (y >= 4) {
                    float t = 0.0f;
                    #pragma unroll
                    for (int d = 0; d < 4; ++d) t += __ldg(hy + (y-4+d) * HYC + (x-1)) * kb[d];
                    s += t;
                }
            }
            // S2
            if (y >= 2 && y <= P-3 && x >= 2 && x <= Q-3) {
                float a = 0.0f;
                #pragma unroll
                for (int di = 0; di < 3; ++di)
                    #pragma unroll
                    for (int dj = 0; dj < 4; ++dj)
                        a += __ldg(hx + (y-2+di) * HXC + (x-2+dj)) * f[di][dj];
                s -= 0.5f * a;
            }
            if (y >= 1 && y <= P-2) {
                if (x <= Q-5) {
                    float t = 0.0f;
                    #pragma unroll
                    for (int d = 0; d < 4; ++d) t += __ldg(hx + (y-1) * HXC + (x+d)) * kf[d];
                    s -= t;
                }
                if (x >= 4) {
                    float t = 0.0f;
                    #pragma unroll
                    for (int d = 0; d < 4; ++d) t += __ldg(hx + (y-1) * HXC + (x-4+d)) * kb[d];
                    s -= t;
                }
            }
            acc[m] = s;
        }
    }

    const float* e = E + b * Eb;
    float* eo = Eout + b * Eob;
    #pragma unroll
    for (int m = 0; m < KY; ++m)
        eo[(Y+m) * Q + x] = __ldg(e + (Y+m) * Q + x) + acc[m];
}

// ===========================================================================
// faraday: Hx_out[i,j] = Hx[i,j] - S3(E);  Hy_out[i,j] = Hy[i,j] + S4(E)
// Thread (tx,ty): col j = j0+tx, rows i = I..I+3, I = i0 + 4*ty.
// ===========================================================================
__global__ __launch_bounds__(NT) void faraday_ldg(
    const float* __restrict__ E,  int Eb,
    const float* __restrict__ Hx, int Hxb,
    const float* __restrict__ Hy, int Hyb,
    const float* __restrict__ filt,
    float* __restrict__ Hxo, int Hxob,
    float* __restrict__ Hyo, int Hyob)
{
    const int j0 = blockIdx.x * TX;
    const int i0 = blockIdx.y * TROWS;
    const int b  = blockIdx.z;
    const int tx = threadIdx.x, ty = threadIdx.y;

    float f[3][4];
    #pragma unroll
    for (int i = 0; i < 12; ++i) (&f[0][0])[i] = __ldg(filt + i);

    const float* e = E + b * Eb;

    const int I = i0 + ty * KY;
    const int j = j0 + tx;

    const bool interior = (i0 >= 2) && (i0 + TROWS <= P - 3) &&
                          (j0 >= 2) && (j0 + TX <= Q - 3);

    if (interior) {
        const float gg[6] = {
            KB0,
            0.5f*f[1][0] + KB1,
            0.5f*f[1][1] + KF0 + KB2,
            0.5f*f[1][2] + KF1 + KB3,
            0.5f*f[1][3] + KF2,
            KF3
        };
        float w0[4], w2[4];
        #pragma unroll
        for (int d = 0; d < 4; ++d) { w0[d] = 0.5f*f[0][d]; w2[d] = 0.5f*f[2][d]; }

        float aHx[KY] = {0.f,0.f,0.f,0.f};
        float aHy[KY] = {0.f,0.f,0.f,0.f};

        {   // col j-2: rows I..I+5
            float v[KY+2];
            #pragma unroll
            for (int t = 0; t < KY+2; ++t) v[t] = __ldg(e + (I+t) * Q + (j-2));
            #pragma unroll
            for (int m = 0; m < KY; ++m) aHx[m] += gg[0]*v[m+1];
        }
        {   // col j-1: rows I..I+5
            float v[KY+2];
            #pragma unroll
            for (int t = 0; t < KY+2; ++t) v[t] = __ldg(e + (I+t) * Q + (j-1));
            #pragma unroll
            for (int m = 0; m < KY; ++m)
                aHx[m] += gg[1]*v[m+1] + w0[0]*v[m] + w2[0]*v[m+2];
        }
        {   // col j: rows I-1..I+5
            float v[KY+3];
            #pragma unroll
            for (int t = 0; t < KY+3; ++t) v[t] = __ldg(e + (I-1+t) * Q + j);
            #pragma unroll
            for (int m = 0; m < KY; ++m) {
                aHx[m] += gg[2]*v[m+2] + w0[1]*v[m+1] + w2[1]*v[m+3];
                #pragma unroll
                for (int d = 0; d < 4; ++d) aHy[m] += w0[d]*v[m+d];
            }
        }
        {   // col j+1: rows I-2..I+6
            float v[KY+5];
            #pragma unroll
            for (int t = 0; t < KY+5; ++t) v[t] = __ldg(e + (I-2+t) * Q + (j+1));
            #pragma unroll
            for (int m = 0; m < KY; ++m) {
                aHx[m] += gg[3]*v[m+3] + w0[2]*v[m+2] + w2[2]*v[m+4];
                #pragma unroll
                for (int t = 0; t < 6; ++t) aHy[m] += gg[t]*v[m+t];
            }
        }
        {   // col j+2: rows I-1..I+5
            float v[KY+3];
            #pragma unroll
            for (int t = 0; t < KY+3; ++t) v[t] = __ldg(e + (I-1+t) * Q + (j+2));
            #pragma unroll
            for (int m = 0; m < KY; ++m) {
                aHx[m] += gg[4]*v[m+2] + w0[3]*v[m+1] + w2[3]*v[m+3];
                #pragma unroll
                for (int d = 0; d < 4; ++d) aHy[m] += w2[d]*v[m+d];
            }
        }
        {   // col j+3: rows I..I+5
            float v[KY+2];
            #pragma unroll
            for (int t = 0; t < KY+2; ++t) v[t] = __ldg(e + (I+t) * Q + (j+3));
            #pragma unroll
            for (int m = 0; m < KY; ++m) aHx[m] += gg[5]*v[m+1];
        }

        const float* hxi = Hx + b * Hxb;
        const float* hyi = Hy + b * Hyb;
        float* hxo = Hxo + b * Hxob;
        float* hyo = Hyo + b * Hyob;
        #pragma unroll
        for (int m = 0; m < KY; ++m) {
            const int i = I + m;
            hxo[i * HXC + j] = __ldg(hxi + i * HXC + j) - aHx[m];
            hyo[i * HYC + j] = __ldg(hyi + i * HYC + j) + aHy[m];
        }
    } else {
        const float kf[4] = {KF0, KF1, KF2, KF3};
        const float kb[4] = {KB0, KB1, KB2, KB3};
        #pragma unroll
        for (int m = 0; m < KY; ++m) {
            const int i = I + m;
            // Hx update: i in [0,HXR), j in [0,HXC)
            if (i < HXR && j < HXC) {
                float s = __ldg(Hx + b * Hxb + i * HXC + j);
                if (j >= 1 && j <= Q-3) {
                    float a = 0.0f;
                    #pragma unroll
                    for (int di = 0; di < 3; ++di)
                        #pragma unroll
                        for (int dj = 0; dj < 4; ++dj)
                            a += __ldg(e + (i+di) * Q + (j-1+dj)) * f[di][dj];
                    s -= 0.5f * a;
                }
                if (j <= Q-4) {
                    float t = 0.0f;
                    #pragma unroll
                    for (int d = 0; d < 4; ++d) t += __ldg(e + (i+1) * Q + (j+d)) * kf[d];
                    s -= t;
                }
                if (j >= 2) {
                    float t = 0.0f;
                    #pragma unroll
                    for (int d = 0; d < 4; ++d) t += __ldg(e + (i+1) * Q + (j-2+d)) * kb[d];
                    s -= t;
                }
                Hxo[b * Hxob + i * HXC + j] = s;
            }
            // Hy update: i in [0,HYR), j in [0,HYC)
            if (i < HYR && j < HYC) {
                float s = __ldg(Hy + b * Hyb + i * HYC + j);
                if (i >= 1 && i <= P-3) {
                    float a = 0.0f;
                    #pragma unroll
                    for (int di = 0; di < 4; ++di)
                        #pragma unroll
                        for (int dj = 0; dj < 3; ++dj)
                            a += __ldg(e + (i-1+di) * Q + (j+dj)) * f[dj][di];
                    s += 0.5f * a;
                }
                if (i <= P-4) {
                    float t = 0.0f;
                    #pragma unroll
                    for (int d = 0; d < 4; ++d) t += __ldg(e + (i+d) * Q + (j+1)) * kf[d];
                    s += t;
                }
                if (i >= 2) {
                    float t = 0.0f;
                    #pragma unroll
                    for (int d = 0; d < 4; ++d) t += __ldg(e + (i-2+d) * Q + (j+1)) * kb[d];
                    s += t;
                }
                Hyo[b * Hyob + i * HYC + j] = s;
            }
        }
    }
}

// ---------------------------------------------------------------------------
// Launch: 2 time steps, results written directly into d_out sections.
// d_out layout:
//   E  : BATCH x (2*P) x Q       @ 0
//   Hx : BATCH x (2*HXR) x HXC   @ BATCH*2*P*Q
//   Hy : BATCH x (2*HYR) x HYC   @ BATCH*2*P*Q + BATCH*2*HXR*HXC
// ---------------------------------------------------------------------------
extern "C" void kernel_launch(void* const* d_in, const int* in_sizes, int n_in,
                              void* d_out, int out_size)
{
    const float* E    = (const float*)d_in[0];
    const float* Hx   = (const float*)d_in[1];
    const float* Hy   = (const float*)d_in[2];
    const float* filt = (const float*)d_in[3];
    float* out = (float*)d_out;

    const int E_IN_B  = P * Q;
    const int HX_IN_B = HXR * HXC;
    const int HY_IN_B = HYR * HYC;

    const int E_OUT_B  = 2 * P * Q;
    const int HX_OUT_B = 2 * HXR * HXC;
    const int HY_OUT_B = 2 * HYR * HYC;

    float* En  = out;
    float* Em  = out + P * Q;
    float* Hxn = out + (long long)BATCH * E_OUT_B;
    float* Hxm = Hxn + HXR * HXC;
    float* Hyn = Hxn + (long long)BATCH * HX_OUT_B;
    float* Hym = Hyn + HYR * HYC;

    dim3 blk(TX, WY, 1);
    dim3 g(Q / TX, P / TROWS, BATCH);   // (32, 32, 8)

    // Step 1
    amper_ldg<<<g, blk>>>(E, E_IN_B, Hx, HX_IN_B, Hy, HY_IN_B, filt,
                          En, E_OUT_B);
    faraday_ldg<<<g, blk>>>(En, E_OUT_B, Hx, HX_IN_B, Hy, HY_IN_B, filt,
                            Hxn, HX_OUT_B, Hyn, HY_OUT_B);
    // Step 2
    amper_ldg<<<g, blk>>>(En, E_OUT_B, Hxn, HX_OUT_B, Hyn, HY_OUT_B, filt,
                          Em, E_OUT_B);
    faraday_ldg<<<g, blk>>>(Em, E_OUT_B, Hxn, HX_OUT_B, Hyn, HY_OUT_B, filt,
                            Hxm, HX_OUT_B, Hym, HY_OUT_B);
}